// round 6
// baseline (speedup 1.0000x reference)
#include <cuda_runtime.h>
#include <cuda_bf16.h>
#include <cstdint>

// Problem constants
#define B_   8
#define T_   1024
#define Cc_  1024
#define H_   16
#define D_   64
#define BH_  (B_*H_)     // 128
#define M_   (B_*T_)     // 8192
#define N3_  3072
#define KE_  (3*Cc_)     // 3072 (split-expanded K)

// Scratch (static device globals: allocation-free)
__device__ __nv_bfloat16 g_Qh[(size_t)BH_*T_*D_], g_Ql[(size_t)BH_*T_*D_];
__device__ __nv_bfloat16 g_Kh[(size_t)BH_*T_*D_], g_Kl[(size_t)BH_*T_*D_];
__device__ __nv_bfloat16 g_Vh[(size_t)BH_*T_*D_], g_Vl[(size_t)BH_*T_*D_];
__device__ __nv_bfloat16 g_Ac[(size_t)M_*KE_];      // A' = [hi|hi|lo]
__device__ __nv_bfloat16 g_Bqkv[(size_t)N3_*KE_];   // B'^T rows: [hi|lo|hi]
__device__ __nv_bfloat16 g_Bout[(size_t)Cc_*KE_];

// ---------------------------------------------------------------------------
__device__ __forceinline__ uint32_t smem_u32(const void* p) {
    uint32_t a;
    asm("{ .reg .u64 t; cvta.to.shared.u64 t, %1; cvt.u32.u64 %0, t; }"
        : "=r"(a) : "l"(p));
    return a;
}
__device__ __forceinline__ void ldsm_x4(uint32_t& r0, uint32_t& r1,
                                        uint32_t& r2, uint32_t& r3, uint32_t addr) {
    asm volatile("ldmatrix.sync.aligned.m8n8.x4.shared.b16 {%0,%1,%2,%3}, [%4];"
                 : "=r"(r0), "=r"(r1), "=r"(r2), "=r"(r3) : "r"(addr));
}
__device__ __forceinline__ void ldsm_x4_t(uint32_t& r0, uint32_t& r1,
                                          uint32_t& r2, uint32_t& r3, uint32_t addr) {
    asm volatile("ldmatrix.sync.aligned.m8n8.x4.trans.shared.b16 {%0,%1,%2,%3}, [%4];"
                 : "=r"(r0), "=r"(r1), "=r"(r2), "=r"(r3) : "r"(addr));
}
__device__ __forceinline__ void mma_bf16(float* d, uint32_t a0, uint32_t a1,
                                         uint32_t a2, uint32_t a3,
                                         uint32_t b0, uint32_t b1) {
    asm volatile(
        "mma.sync.aligned.m16n8k16.row.col.f32.bf16.bf16.f32 "
        "{%0,%1,%2,%3}, {%4,%5,%6,%7}, {%8,%9}, {%0,%1,%2,%3};"
        : "+f"(d[0]), "+f"(d[1]), "+f"(d[2]), "+f"(d[3])
        : "r"(a0), "r"(a1), "r"(a2), "r"(a3), "r"(b0), "r"(b1));
}
__device__ __forceinline__ void cp_async16(uint32_t saddr, const void* gaddr) {
    asm volatile("cp.async.cg.shared.global [%0], [%1], 16;"
                 :: "r"(saddr), "l"(gaddr));
}
#define CP_COMMIT() asm volatile("cp.async.commit_group;" ::: "memory")
#define CP_WAIT(n)  asm volatile("cp.async.wait_group %0;" :: "n"(n) : "memory")

__device__ __forceinline__ void split4_bf16(float4 v, uint2& hi, uint2& lo) {
    float f[4] = {v.x, v.y, v.z, v.w};
    unsigned short h[4], l[4];
#pragma unroll
    for (int i = 0; i < 4; i++) {
        __nv_bfloat16 hb = __float2bfloat16(f[i]);
        float r = f[i] - __bfloat162float(hb);
        __nv_bfloat16 lb = __float2bfloat16(r);
        h[i] = __bfloat16_as_ushort(hb);
        l[i] = __bfloat16_as_ushort(lb);
    }
    hi = make_uint2((uint32_t)h[0] | ((uint32_t)h[1] << 16),
                    (uint32_t)h[2] | ((uint32_t)h[3] << 16));
    lo = make_uint2((uint32_t)l[0] | ((uint32_t)l[1] << 16),
                    (uint32_t)l[2] | ((uint32_t)l[3] << 16));
}
__device__ __forceinline__ void split2_pack(float x, float y, uint32_t& hi, uint32_t& lo) {
    __nv_bfloat16 hx = __float2bfloat16(x), hy = __float2bfloat16(y);
    __nv_bfloat16 lx = __float2bfloat16(x - __bfloat162float(hx));
    __nv_bfloat16 ly = __float2bfloat16(y - __bfloat162float(hy));
    hi = (uint32_t)__bfloat16_as_ushort(hx) | ((uint32_t)__bfloat16_as_ushort(hy) << 16);
    lo = (uint32_t)__bfloat16_as_ushort(lx) | ((uint32_t)__bfloat16_as_ushort(ly) << 16);
}

// ---------------------------------------------------------------------------
// Conversion kernels
// ---------------------------------------------------------------------------
__global__ __launch_bounds__(256)
void conv_act(const float* __restrict__ src)
{
    int idx = blockIdx.x * 256 + threadIdx.x;
    int m  = idx >> 8;
    int k4 = (idx & 255) << 2;
    float4 v = *(const float4*)(src + (size_t)m * Cc_ + k4);
    uint2 hi, lo;
    split4_bf16(v, hi, lo);
    __nv_bfloat16* drow = g_Ac + (size_t)m * KE_;
    *(uint2*)(drow + k4)         = hi;
    *(uint2*)(drow + Cc_ + k4)   = hi;
    *(uint2*)(drow + 2*Cc_ + k4) = lo;
}

template<int WSEL>  // 1: g_Bqkv, 0: g_Bout
__global__ __launch_bounds__(256)
void conv_w(const float* __restrict__ W, int N)
{
    __shared__ float tile[32][33];
    __nv_bfloat16* Bt = WSEL ? g_Bqkv : g_Bout;
    const int k0 = blockIdx.x * 32, n0 = blockIdx.y * 32;
    const int t = threadIdx.x;
#pragma unroll
    for (int i = 0; i < 4; i++) {
        int r = (t >> 5) + i * 8;
        int c = t & 31;
        tile[r][c] = W[(size_t)(k0 + r) * N + n0 + c];
    }
    __syncthreads();
#pragma unroll
    for (int i = 0; i < 4; i++) {
        int nr = (t >> 5) + i * 8;
        int kc = t & 31;
        float v = tile[kc][nr];
        __nv_bfloat16 hb = __float2bfloat16(v);
        float res = v - __bfloat162float(hb);
        __nv_bfloat16 lb = __float2bfloat16(res);
        __nv_bfloat16* row = Bt + (size_t)(n0 + nr) * KE_;
        row[k0 + kc]         = hb;
        row[Cc_ + k0 + kc]   = lb;
        row[2*Cc_ + k0 + kc] = hb;
    }
}

// ---------------------------------------------------------------------------
// Pipelined bf16 HMMA GEMM: 256x128 CTA tile, BK=64, 8 warps (4M x 2N),
// warp tile 64x64, 3-stage cp.async pipeline. K_eff=3072.
// MODE 1: epilogue -> split Q/K/V bf16 hi/lo [B,H,T,D] (Q pre-scaled).
// MODE 0: plain fp32 out (+bias).
// ---------------------------------------------------------------------------
#define TSTRIDE 72
#define ATILE_B (256*TSTRIDE*2)          // 36864
#define BTILE_B (128*TSTRIDE*2)          // 18432
#define STAGE_B (ATILE_B + BTILE_B)      // 55296
#define NSTAGE  3
#define GSMEM_TOTAL (NSTAGE*STAGE_B)     // 165888
#define NCH     (KE_/64)                 // 48

template<int MODE>
__global__ __launch_bounds__(256, 1)
void tgemm_kernel(const float* __restrict__ bias,
                  float* __restrict__ Cout,
                  int N)
{
    extern __shared__ char smc[];
    const uint32_t sb = smem_u32(smc);
    const int tid = threadIdx.x;
    const int wid = tid >> 5, lane = tid & 31;
    const int bx = blockIdx.x, by = blockIdx.y;
    const int wm = wid & 3;          // 64 rows each
    const int wn = wid >> 2;         // 64 cols each

    const __nv_bfloat16* Abf = g_Ac + (size_t)(by * 256) * KE_;
    const __nv_bfloat16* Bbf = (MODE ? g_Bqkv : g_Bout) + (size_t)(bx * 128) * KE_;

    const int lrow = tid >> 3;          // 0..31
    const int lch  = tid & 7;           // 0..7
    const uint32_t sOff = (uint32_t)(lrow * TSTRIDE * 2 + lch * 16);

    float acc[4][8][4];
#pragma unroll
    for (int i = 0; i < 4; i++)
#pragma unroll
        for (int j = 0; j < 8; j++)
#pragma unroll
            for (int v = 0; v < 4; v++) acc[i][j][v] = 0.f;

    const int a_row = (lane & 7) + ((lane >> 3) & 1) * 8;
    const int a_col = (lane >> 4) * 8;
    const int b_row = (lane & 7) + (lane >> 4) * 8;
    const int b_col = ((lane >> 3) & 1) * 8;
    const uint32_t aBaseRow = (uint32_t)(wm * 64 + a_row);
    const uint32_t bBaseRow = (uint32_t)(wn * 64 + b_row);

    auto load_stage = [&](int st, int ch) {
        const uint32_t sA = sb + st * STAGE_B + sOff;
        const uint32_t sB = sA + ATILE_B;
        const __nv_bfloat16* Ag = Abf + (size_t)lrow * KE_ + ch * 64 + lch * 8;
        const __nv_bfloat16* Bg = Bbf + (size_t)lrow * KE_ + ch * 64 + lch * 8;
#pragma unroll
        for (int i = 0; i < 8; i++)
            cp_async16(sA + i * 32 * TSTRIDE * 2, Ag + (size_t)(i * 32) * KE_);
#pragma unroll
        for (int i = 0; i < 4; i++)
            cp_async16(sB + i * 32 * TSTRIDE * 2, Bg + (size_t)(i * 32) * KE_);
    };

#pragma unroll
    for (int s = 0; s < NSTAGE - 1; ++s) {
        load_stage(s, s);
        CP_COMMIT();
    }

    for (int ch = 0; ch < NCH; ++ch) {
        const int lc = ch + NSTAGE - 1;
        if (lc < NCH) load_stage(lc % NSTAGE, lc);
        CP_COMMIT();
        CP_WAIT(NSTAGE - 1);
        __syncthreads();

        const uint32_t sAp = sb + (ch % NSTAGE) * STAGE_B;
        const uint32_t sBp = sAp + ATILE_B;
#pragma unroll
        for (int kk = 0; kk < 4; ++kk) {
            const int kc = kk * 16;
            uint32_t a[4][4];
#pragma unroll
            for (int mt = 0; mt < 4; ++mt) {
                uint32_t addr = sAp + ((aBaseRow + mt * 16) * TSTRIDE + kc + a_col) * 2;
                ldsm_x4(a[mt][0], a[mt][1], a[mt][2], a[mt][3], addr);
            }
            uint32_t b[8][2];
#pragma unroll
            for (int np = 0; np < 4; ++np) {
                uint32_t addr = sBp + ((bBaseRow + np * 16) * TSTRIDE + kc + b_col) * 2;
                uint32_t r0, r1, r2, r3;
                ldsm_x4(r0, r1, r2, r3, addr);
                b[np*2][0] = r0; b[np*2][1] = r1;
                b[np*2+1][0] = r2; b[np*2+1][1] = r3;
            }
#pragma unroll
            for (int mt = 0; mt < 4; ++mt)
#pragma unroll
                for (int nt = 0; nt < 8; ++nt)
                    mma_bf16(acc[mt][nt], a[mt][0], a[mt][1], a[mt][2], a[mt][3],
                             b[nt][0], b[nt][1]);
        }
        __syncthreads();
    }

    // -------- epilogue --------
    const int tr = lane >> 2;
    const int tc = (lane & 3) * 2;
#pragma unroll
    for (int mt = 0; mt < 4; ++mt) {
#pragma unroll
        for (int nt = 0; nt < 8; ++nt) {
            const int col = bx * 128 + wn * 64 + nt * 8 + tc;
            const float b0 = __ldg(bias + col);
            const float b1 = __ldg(bias + col + 1);
#pragma unroll
            for (int h2 = 0; h2 < 2; ++h2) {
                const int m = by * 256 + wm * 64 + mt * 16 + h2 * 8 + tr;
                float ox = acc[mt][nt][h2*2+0] + b0;
                float oy = acc[mt][nt][h2*2+1] + b1;
                if (MODE == 0) {
                    *(float2*)(Cout + (size_t)m * N + col) = make_float2(ox, oy);
                } else {
                    const int seg = col >> 10;
                    const int c = col & 1023;
                    const int h = c >> 6;
                    const int d = c & 63;
                    const int bb = m >> 10, t = m & 1023;
                    if (seg == 0) { ox *= 0.125f; oy *= 0.125f; }  // fold 1/sqrt(D)
                    uint32_t hw, lw;
                    split2_pack(ox, oy, hw, lw);
                    size_t idx = (((size_t)(bb * H_ + h)) * T_ + t) * D_ + d;
                    __nv_bfloat16 *dh, *dl;
                    if (seg == 0)      { dh = g_Qh; dl = g_Ql; }
                    else if (seg == 1) { dh = g_Kh; dl = g_Kl; }
                    else               { dh = g_Vh; dl = g_Vl; }
                    *(uint32_t*)(dh + idx) = hw;
                    *(uint32_t*)(dl + idx) = lw;
                }
            }
        }
    }
}

// ---------------------------------------------------------------------------
// HMMA flash attention (unchanged from R5)
// ---------------------------------------------------------------------------
#define AST 72
#define QH_OFF 0
#define QL_OFF (128*AST*2)
#define STG0   (2*128*AST*2)
#define KTILE_B (64*AST*2)
#define STG_B  (4*KTILE_B)
#define ASMEM_TOTAL (STG0 + 2*STG_B)   // 110592

__global__ __launch_bounds__(256)
void attn_kernel()
{
    extern __shared__ char smc[];
    const uint32_t sb = smem_u32(smc);
    const int tid = threadIdx.x, wid = tid >> 5, lane = tid & 31;
    const int qt = blockIdx.x, bh = blockIdx.y;
    const int q0 = qt * 128;
    const size_t base = (size_t)bh * T_ * D_;

    {
        const __nv_bfloat16* Qh = g_Qh + base + (size_t)q0 * D_;
        const __nv_bfloat16* Ql = g_Ql + base + (size_t)q0 * D_;
#pragma unroll
        for (int i = 0; i < 4; i++) {
            int idx = tid + i * 256;
            int r = idx >> 3, c = idx & 7;
            cp_async16(sb + QH_OFF + (uint32_t)(r * AST + c * 8) * 2, Qh + (size_t)r * 64 + c * 8);
            cp_async16(sb + QL_OFF + (uint32_t)(r * AST + c * 8) * 2, Ql + (size_t)r * 64 + c * 8);
        }
        CP_COMMIT();
    }

    const int KT = 2 * qt + 2;

    auto load_stage = [&](int st, int kt) {
        const uint32_t s0 = sb + STG0 + st * STG_B;
        const __nv_bfloat16* srcs[4] = {
            g_Kh + base + (size_t)kt * 64 * D_,
            g_Kl + base + (size_t)kt * 64 * D_,
            g_Vh + base + (size_t)kt * 64 * D_,
            g_Vl + base + (size_t)kt * 64 * D_ };
#pragma unroll
        for (int tg = 0; tg < 4; tg++) {
#pragma unroll
            for (int it = 0; it < 2; it++) {
                int r = (tid >> 3) + it * 32, c = tid & 7;
                cp_async16(s0 + tg * KTILE_B + (uint32_t)(r * AST + c * 8) * 2,
                           srcs[tg] + (size_t)r * 64 + c * 8);
            }
        }
    };

    load_stage(0, 0); CP_COMMIT();

    const int a_row = (lane & 7) + ((lane >> 3) & 1) * 8;
    const int a_col = (lane >> 4) * 8;
    const int b_row = (lane & 7) + (lane >> 4) * 8;
    const int b_col = ((lane >> 3) & 1) * 8;
    const int v_row = lane & 15;
    const int v_col = (lane >> 4) * 8;
    const int wm = wid;

    uint32_t qh[4][4], ql[4][4];
    float m_[2] = {-1e30f, -1e30f}, l_[2] = {0.f, 0.f};
    float oacc[8][4];
#pragma unroll
    for (int i = 0; i < 8; i++)
#pragma unroll
        for (int v = 0; v < 4; v++) oacc[i][v] = 0.f;

    const int rbase = q0 + wm * 16;

    for (int kt = 0; kt < KT; ++kt) {
        if (kt + 1 < KT) { load_stage((kt + 1) & 1, kt + 1); CP_COMMIT(); CP_WAIT(1); }
        else             { CP_WAIT(0); }
        __syncthreads();

        if (kt == 0) {
#pragma unroll
            for (int ks = 0; ks < 4; ks++) {
                uint32_t aq = sb + QH_OFF + (uint32_t)((wm * 16 + a_row) * AST + ks * 16 + a_col) * 2;
                ldsm_x4(qh[ks][0], qh[ks][1], qh[ks][2], qh[ks][3], aq);
                ldsm_x4(ql[ks][0], ql[ks][1], ql[ks][2], ql[ks][3], aq + (QL_OFF - QH_OFF));
            }
        }

        const bool active = (kt * 64) <= (rbase + 15);
        if (active) {
            const uint32_t sKh = sb + STG0 + (kt & 1) * STG_B;
            const uint32_t sKl = sKh + KTILE_B;
            const uint32_t sVh = sKh + 2 * KTILE_B;
            const uint32_t sVl = sKh + 3 * KTILE_B;

            float sacc[8][4];
#pragma unroll
            for (int i = 0; i < 8; i++)
#pragma unroll
                for (int v = 0; v < 4; v++) sacc[i][v] = 0.f;

#pragma unroll
            for (int ks = 0; ks < 4; ks++) {
                uint32_t kf[4][4];
#pragma unroll
                for (int np = 0; np < 4; np++) {
                    uint32_t addr = sKh + (uint32_t)((np * 16 + b_row) * AST + ks * 16 + b_col) * 2;
                    ldsm_x4(kf[np][0], kf[np][1], kf[np][2], kf[np][3], addr);
                }
#pragma unroll
                for (int np = 0; np < 4; np++) {
                    mma_bf16(sacc[2*np],   qh[ks][0], qh[ks][1], qh[ks][2], qh[ks][3], kf[np][0], kf[np][1]);
                    mma_bf16(sacc[2*np+1], qh[ks][0], qh[ks][1], qh[ks][2], qh[ks][3], kf[np][2], kf[np][3]);
                    mma_bf16(sacc[2*np],   ql[ks][0], ql[ks][1], ql[ks][2], ql[ks][3], kf[np][0], kf[np][1]);
                    mma_bf16(sacc[2*np+1], ql[ks][0], ql[ks][1], ql[ks][2], ql[ks][3], kf[np][2], kf[np][3]);
                }
#pragma unroll
                for (int np = 0; np < 4; np++) {
                    uint32_t addr = sKl + (uint32_t)((np * 16 + b_row) * AST + ks * 16 + b_col) * 2;
                    ldsm_x4(kf[np][0], kf[np][1], kf[np][2], kf[np][3], addr);
                }
#pragma unroll
                for (int np = 0; np < 4; np++) {
                    mma_bf16(sacc[2*np],   qh[ks][0], qh[ks][1], qh[ks][2], qh[ks][3], kf[np][0], kf[np][1]);
                    mma_bf16(sacc[2*np+1], qh[ks][0], qh[ks][1], qh[ks][2], qh[ks][3], kf[np][2], kf[np][3]);
                }
            }

            if (kt * 64 + 63 > rbase) {
                const int r0r = rbase + (lane >> 2);
#pragma unroll
                for (int nt = 0; nt < 8; nt++) {
#pragma unroll
                    for (int v = 0; v < 4; v++) {
                        int col = kt * 64 + nt * 8 + 2 * (lane & 3) + (v & 1);
                        int row = r0r + (v >> 1) * 8;
                        if (col > row) sacc[nt][v] = -1e30f;
                    }
                }
            }

            float alpha[2];
#pragma unroll
            for (int h2 = 0; h2 < 2; h2++) {
                float mx = -1e30f;
#pragma unroll
                for (int nt = 0; nt < 8; nt++)
                    mx = fmaxf(mx, fmaxf(sacc[nt][2*h2], sacc[nt][2*h2+1]));
                mx = fmaxf(mx, __shfl_xor_sync(0xffffffffu, mx, 1));
                mx = fmaxf(mx, __shfl_xor_sync(0xffffffffu, mx, 2));
                float mnew = fmaxf(m_[h2], mx);
                alpha[h2] = __expf(m_[h2] - mnew);
                float rs = 0.f;
#pragma unroll
                for (int nt = 0; nt < 8; nt++) {
                    sacc[nt][2*h2]   = __expf(sacc[nt][2*h2]   - mnew);
                    sacc[nt][2*h2+1] = __expf(sacc[nt][2*h2+1] - mnew);
                    rs += sacc[nt][2*h2] + sacc[nt][2*h2+1];
                }
                rs += __shfl_xor_sync(0xffffffffu, rs, 1);
                rs += __shfl_xor_sync(0xffffffffu, rs, 2);
                l_[h2] = l_[h2] * alpha[h2] + rs;
                m_[h2] = mnew;
            }
#pragma unroll
            for (int dt = 0; dt < 8; dt++) {
                oacc[dt][0] *= alpha[0]; oacc[dt][1] *= alpha[0];
                oacc[dt][2] *= alpha[1]; oacc[dt][3] *= alpha[1];
            }

#pragma unroll
            for (int ks = 0; ks < 4; ks++) {
                uint32_t ph[4], pl[4];
                split2_pack(sacc[2*ks][0],   sacc[2*ks][1],   ph[0], pl[0]);
                split2_pack(sacc[2*ks][2],   sacc[2*ks][3],   ph[1], pl[1]);
                split2_pack(sacc[2*ks+1][0], sacc[2*ks+1][1], ph[2], pl[2]);
                split2_pack(sacc[2*ks+1][2], sacc[2*ks+1][3], ph[3], pl[3]);

                uint32_t vf[4][4];
#pragma unroll
                for (int nt2 = 0; nt2 < 4; nt2++) {
                    uint32_t addr = sVh + (uint32_t)((ks * 16 + v_row) * AST + nt2 * 16 + v_col) * 2;
                    ldsm_x4_t(vf[nt2][0], vf[nt2][1], vf[nt2][2], vf[nt2][3], addr);
                }
#pragma unroll
                for (int nt2 = 0; nt2 < 4; nt2++) {
                    mma_bf16(oacc[2*nt2],   ph[0], ph[1], ph[2], ph[3], vf[nt2][0], vf[nt2][1]);
                    mma_bf16(oacc[2*nt2+1], ph[0], ph[1], ph[2], ph[3], vf[nt2][2], vf[nt2][3]);
                    mma_bf16(oacc[2*nt2],   pl[0], pl[1], pl[2], pl[3], vf[nt2][0], vf[nt2][1]);
                    mma_bf16(oacc[2*nt2+1], pl[0], pl[1], pl[2], pl[3], vf[nt2][2], vf[nt2][3]);
                }
#pragma unroll
                for (int nt2 = 0; nt2 < 4; nt2++) {
                    uint32_t addr = sVl + (uint32_t)((ks * 16 + v_row) * AST + nt2 * 16 + v_col) * 2;
                    ldsm_x4_t(vf[nt2][0], vf[nt2][1], vf[nt2][2], vf[nt2][3], addr);
                }
#pragma unroll
                for (int nt2 = 0; nt2 < 4; nt2++) {
                    mma_bf16(oacc[2*nt2],   ph[0], ph[1], ph[2], ph[3], vf[nt2][0], vf[nt2][1]);
                    mma_bf16(oacc[2*nt2+1], ph[0], ph[1], ph[2], ph[3], vf[nt2][2], vf[nt2][3]);
                }
            }
        }
        __syncthreads();
    }

    const int bb = bh >> 4, hh = bh & 15;
    const float inv0 = 1.f / l_[0], inv1 = 1.f / l_[1];
#pragma unroll
    for (int dt = 0; dt < 8; dt++) {
#pragma unroll
        for (int h2 = 0; h2 < 2; h2++) {
            const int rloc = wm * 16 + (lane >> 2) + h2 * 8;
            const int d = dt * 8 + 2 * (lane & 3);
            const float inv = h2 ? inv1 : inv0;
            float ox = oacc[dt][2*h2]   * inv;
            float oy = oacc[dt][2*h2+1] * inv;
            uint32_t hw, lw;
            split2_pack(ox, oy, hw, lw);
            const size_t mrow = (size_t)(bb * T_ + q0 + rloc);
            __nv_bfloat16* row = g_Ac + mrow * KE_ + hh * 64 + d;
            *(uint32_t*)(row)          = hw;
            *(uint32_t*)(row + Cc_)    = hw;
            *(uint32_t*)(row + 2*Cc_)  = lw;
        }
    }
}

// ---------------------------------------------------------------------------
extern "C" void kernel_launch(void* const* d_in, const int* in_sizes, int n_in,
                              void* d_out, int out_size)
{
    const float* x    = (const float*)d_in[0];
    const float* Wqkv = (const float*)d_in[1];
    const float* bqkv = (const float*)d_in[2];
    const float* Wout = (const float*)d_in[3];
    const float* bout = (const float*)d_in[4];
    float* out = (float*)d_out;

    cudaFuncSetAttribute(tgemm_kernel<1>,
                         cudaFuncAttributeMaxDynamicSharedMemorySize, GSMEM_TOTAL);
    cudaFuncSetAttribute(tgemm_kernel<0>,
                         cudaFuncAttributeMaxDynamicSharedMemorySize, GSMEM_TOTAL);
    cudaFuncSetAttribute(attn_kernel,
                         cudaFuncAttributeMaxDynamicSharedMemorySize, ASMEM_TOTAL);

    // 0) split conversions
    conv_w<1><<<dim3(Cc_/32, N3_/32), 256>>>(Wqkv, N3_);
    conv_w<0><<<dim3(Cc_/32, Cc_/32), 256>>>(Wout, Cc_);
    conv_act<<<M_*Cc_/4/256, 256>>>(x);

    // 1) QKV projection -> Q/K/V bf16 hi/lo [B,H,T,D] (Q pre-scaled)
    tgemm_kernel<1><<<dim3(N3_/128, M_/256), 256, GSMEM_TOTAL>>>(bqkv, nullptr, N3_);

    // 2) HMMA causal flash attention -> g_Ac (split-expanded)
    attn_kernel<<<dim3(T_/128, BH_), 256, ASMEM_TOTAL>>>();

    // 3) output projection -> d_out
    tgemm_kernel<0><<<dim3(Cc_/128, M_/256), 256, GSMEM_TOTAL>>>(bout, out, Cc_);
}

// round 7
// speedup vs baseline: 1.1076x; 1.1076x over previous
#include <cuda_runtime.h>
#include <cuda_bf16.h>
#include <cstdint>

// Problem constants
#define B_   8
#define T_   1024
#define Cc_  1024
#define H_   16
#define D_   64
#define BH_  (B_*H_)     // 128
#define M_   (B_*T_)     // 8192
#define N3_  3072
#define KE_  (3*Cc_)     // 3072 (split-expanded K)

// Scratch (static device globals: allocation-free)
__device__ __nv_bfloat16 g_Qh[(size_t)BH_*T_*D_], g_Ql[(size_t)BH_*T_*D_];
__device__ __nv_bfloat16 g_Kh[(size_t)BH_*T_*D_], g_Kl[(size_t)BH_*T_*D_];
__device__ __nv_bfloat16 g_Vh[(size_t)BH_*T_*D_], g_Vl[(size_t)BH_*T_*D_];
__device__ __nv_bfloat16 g_Ac[(size_t)M_*KE_];      // A' = [hi|hi|lo]
__device__ __nv_bfloat16 g_Bqkv[(size_t)N3_*KE_];   // B'^T rows: [hi|lo|hi]
__device__ __nv_bfloat16 g_Bout[(size_t)Cc_*KE_];

// ---------------------------------------------------------------------------
__device__ __forceinline__ uint32_t smem_u32(const void* p) {
    uint32_t a;
    asm("{ .reg .u64 t; cvta.to.shared.u64 t, %1; cvt.u32.u64 %0, t; }"
        : "=r"(a) : "l"(p));
    return a;
}
__device__ __forceinline__ void ldsm_x4(uint32_t& r0, uint32_t& r1,
                                        uint32_t& r2, uint32_t& r3, uint32_t addr) {
    asm volatile("ldmatrix.sync.aligned.m8n8.x4.shared.b16 {%0,%1,%2,%3}, [%4];"
                 : "=r"(r0), "=r"(r1), "=r"(r2), "=r"(r3) : "r"(addr));
}
__device__ __forceinline__ void ldsm_x4_t(uint32_t& r0, uint32_t& r1,
                                          uint32_t& r2, uint32_t& r3, uint32_t addr) {
    asm volatile("ldmatrix.sync.aligned.m8n8.x4.trans.shared.b16 {%0,%1,%2,%3}, [%4];"
                 : "=r"(r0), "=r"(r1), "=r"(r2), "=r"(r3) : "r"(addr));
}
__device__ __forceinline__ void mma_bf16(float* d, uint32_t a0, uint32_t a1,
                                         uint32_t a2, uint32_t a3,
                                         uint32_t b0, uint32_t b1) {
    asm volatile(
        "mma.sync.aligned.m16n8k16.row.col.f32.bf16.bf16.f32 "
        "{%0,%1,%2,%3}, {%4,%5,%6,%7}, {%8,%9}, {%0,%1,%2,%3};"
        : "+f"(d[0]), "+f"(d[1]), "+f"(d[2]), "+f"(d[3])
        : "r"(a0), "r"(a1), "r"(a2), "r"(a3), "r"(b0), "r"(b1));
}
__device__ __forceinline__ void cp_async16(uint32_t saddr, const void* gaddr) {
    asm volatile("cp.async.cg.shared.global [%0], [%1], 16;"
                 :: "r"(saddr), "l"(gaddr));
}
#define CP_COMMIT() asm volatile("cp.async.commit_group;" ::: "memory")
#define CP_WAIT(n)  asm volatile("cp.async.wait_group %0;" :: "n"(n) : "memory")

__device__ __forceinline__ void split4_bf16(float4 v, uint2& hi, uint2& lo) {
    float f[4] = {v.x, v.y, v.z, v.w};
    unsigned short h[4], l[4];
#pragma unroll
    for (int i = 0; i < 4; i++) {
        __nv_bfloat16 hb = __float2bfloat16(f[i]);
        float r = f[i] - __bfloat162float(hb);
        __nv_bfloat16 lb = __float2bfloat16(r);
        h[i] = __bfloat16_as_ushort(hb);
        l[i] = __bfloat16_as_ushort(lb);
    }
    hi = make_uint2((uint32_t)h[0] | ((uint32_t)h[1] << 16),
                    (uint32_t)h[2] | ((uint32_t)h[3] << 16));
    lo = make_uint2((uint32_t)l[0] | ((uint32_t)l[1] << 16),
                    (uint32_t)l[2] | ((uint32_t)l[3] << 16));
}
__device__ __forceinline__ void split2_pack(float x, float y, uint32_t& hi, uint32_t& lo) {
    __nv_bfloat16 hx = __float2bfloat16(x), hy = __float2bfloat16(y);
    __nv_bfloat16 lx = __float2bfloat16(x - __bfloat162float(hx));
    __nv_bfloat16 ly = __float2bfloat16(y - __bfloat162float(hy));
    hi = (uint32_t)__bfloat16_as_ushort(hx) | ((uint32_t)__bfloat16_as_ushort(hy) << 16);
    lo = (uint32_t)__bfloat16_as_ushort(lx) | ((uint32_t)__bfloat16_as_ushort(ly) << 16);
}

// ---------------------------------------------------------------------------
// Conversion kernels
// ---------------------------------------------------------------------------
__global__ __launch_bounds__(256)
void conv_act(const float* __restrict__ src)
{
    int idx = blockIdx.x * 256 + threadIdx.x;
    int m  = idx >> 8;
    int k4 = (idx & 255) << 2;
    float4 v = *(const float4*)(src + (size_t)m * Cc_ + k4);
    uint2 hi, lo;
    split4_bf16(v, hi, lo);
    __nv_bfloat16* drow = g_Ac + (size_t)m * KE_;
    *(uint2*)(drow + k4)         = hi;
    *(uint2*)(drow + Cc_ + k4)   = hi;
    *(uint2*)(drow + 2*Cc_ + k4) = lo;
}

template<int WSEL>  // 1: g_Bqkv, 0: g_Bout
__global__ __launch_bounds__(256)
void conv_w(const float* __restrict__ W, int N)
{
    __shared__ float tile[32][33];
    __nv_bfloat16* Bt = WSEL ? g_Bqkv : g_Bout;
    const int k0 = blockIdx.x * 32, n0 = blockIdx.y * 32;
    const int t = threadIdx.x;
#pragma unroll
    for (int i = 0; i < 4; i++) {
        int r = (t >> 5) + i * 8;
        int c = t & 31;
        tile[r][c] = W[(size_t)(k0 + r) * N + n0 + c];
    }
    __syncthreads();
#pragma unroll
    for (int i = 0; i < 4; i++) {
        int nr = (t >> 5) + i * 8;
        int kc = t & 31;
        float v = tile[kc][nr];
        __nv_bfloat16 hb = __float2bfloat16(v);
        float res = v - __bfloat162float(hb);
        __nv_bfloat16 lb = __float2bfloat16(res);
        __nv_bfloat16* row = Bt + (size_t)(n0 + nr) * KE_;
        row[k0 + kc]         = hb;
        row[Cc_ + k0 + kc]   = lb;
        row[2*Cc_ + k0 + kc] = hb;
    }
}

// ---------------------------------------------------------------------------
// Pipelined bf16 HMMA GEMM: 128x128 CTA tile, BK=64, 8 warps (4M x 2N),
// warp tile 32x64, 3-stage cp.async, ONE barrier per chunk, B-fragment
// double-buffering across kk-steps. K_eff=3072.
// MODE 1: epilogue -> split Q/K/V bf16 hi/lo (Q pre-scaled). MODE 0: fp32 out.
// ---------------------------------------------------------------------------
#define TSTRIDE 72
#define TILE_B  (128*TSTRIDE*2)
#define STAGE_B (2*TILE_B)
#define NSTAGE  3
#define GSMEM_TOTAL (NSTAGE*STAGE_B)     // 110592
#define NCH     (KE_/64)                 // 48

template<int MODE>
__global__ __launch_bounds__(256)
void tgemm_kernel(const float* __restrict__ bias,
                  float* __restrict__ Cout,
                  int N)
{
    extern __shared__ char smc[];
    const uint32_t sb = smem_u32(smc);
    const int tid = threadIdx.x;
    const int wid = tid >> 5, lane = tid & 31;
    const int bx = blockIdx.x, by = blockIdx.y;
    const int wm = wid & 3;
    const int wn = wid >> 2;

    const __nv_bfloat16* Abf = g_Ac + (size_t)(by * 128) * KE_;
    const __nv_bfloat16* Bbf = (MODE ? g_Bqkv : g_Bout) + (size_t)(bx * 128) * KE_;

    const int lrow = tid >> 3;
    const int lch  = tid & 7;
    const uint32_t sAoff = (uint32_t)(lrow * TSTRIDE * 2 + lch * 16);

    float acc[2][8][4];
#pragma unroll
    for (int i = 0; i < 2; i++)
#pragma unroll
        for (int j = 0; j < 8; j++)
#pragma unroll
            for (int v = 0; v < 4; v++) acc[i][j][v] = 0.f;

    const int a_row = (lane & 7) + ((lane >> 3) & 1) * 8;
    const int a_col = (lane >> 4) * 8;
    const int b_row = (lane & 7) + (lane >> 4) * 8;
    const int b_col = ((lane >> 3) & 1) * 8;
    const uint32_t aBaseRow = (uint32_t)(wm * 32 + a_row);
    const uint32_t bBaseRow = (uint32_t)(wn * 64 + b_row);

    auto load_stage = [&](int st, int ch) {
        const uint32_t sA = sb + st * STAGE_B + sAoff;
        const uint32_t sB = sA + TILE_B;
        const __nv_bfloat16* Ag = Abf + (size_t)lrow * KE_ + ch * 64 + lch * 8;
        const __nv_bfloat16* Bg = Bbf + (size_t)lrow * KE_ + ch * 64 + lch * 8;
#pragma unroll
        for (int i = 0; i < 4; i++) {
            cp_async16(sA + i * 32 * TSTRIDE * 2, Ag + (size_t)(i * 32) * KE_);
            cp_async16(sB + i * 32 * TSTRIDE * 2, Bg + (size_t)(i * 32) * KE_);
        }
    };

    auto load_b = [&](uint32_t sBp, int kk, uint32_t (*bf)[2]) {
        const int kc = kk * 16;
#pragma unroll
        for (int np = 0; np < 4; ++np) {
            uint32_t addr = sBp + ((bBaseRow + np * 16) * TSTRIDE + kc + b_col) * 2;
            uint32_t r0, r1, r2, r3;
            ldsm_x4(r0, r1, r2, r3, addr);
            bf[np*2][0] = r0; bf[np*2][1] = r1;
            bf[np*2+1][0] = r2; bf[np*2+1][1] = r3;
        }
    };

    // prologue: stages 0..NSTAGE-2
#pragma unroll
    for (int s = 0; s < NSTAGE - 1; ++s) {
        load_stage(s, s);
        CP_COMMIT();
    }

    for (int ch = 0; ch < NCH; ++ch) {
        CP_WAIT(NSTAGE - 2);     // stage ch resident
        __syncthreads();         // also: all warps done reading stage (ch-1)

        // issue next stage loads AFTER the barrier (targets stage read at ch-1)
        const int lc = ch + NSTAGE - 1;
        if (lc < NCH) load_stage(lc % NSTAGE, lc);
        CP_COMMIT();

        const uint32_t sAp = sb + (ch % NSTAGE) * STAGE_B;
        const uint32_t sBp = sAp + TILE_B;

        uint32_t bfr[2][8][2];
        load_b(sBp, 0, bfr[0]);
#pragma unroll
        for (int kk = 0; kk < 4; ++kk) {
            if (kk < 3) load_b(sBp, kk + 1, bfr[(kk + 1) & 1]);
            const int kc = kk * 16;
            uint32_t a[2][4];
#pragma unroll
            for (int mt = 0; mt < 2; ++mt) {
                uint32_t addr = sAp + ((aBaseRow + mt * 16) * TSTRIDE + kc + a_col) * 2;
                ldsm_x4(a[mt][0], a[mt][1], a[mt][2], a[mt][3], addr);
            }
            uint32_t (*b)[2] = bfr[kk & 1];
#pragma unroll
            for (int mt = 0; mt < 2; ++mt)
#pragma unroll
                for (int nt = 0; nt < 8; ++nt)
                    mma_bf16(acc[mt][nt], a[mt][0], a[mt][1], a[mt][2], a[mt][3],
                             b[nt][0], b[nt][1]);
        }
    }

    // -------- epilogue --------
    const int tr = lane >> 2;
    const int tc = (lane & 3) * 2;
#pragma unroll
    for (int mt = 0; mt < 2; ++mt) {
#pragma unroll
        for (int nt = 0; nt < 8; ++nt) {
            const int col = bx * 128 + wn * 64 + nt * 8 + tc;
            const float b0 = __ldg(bias + col);
            const float b1 = __ldg(bias + col + 1);
#pragma unroll
            for (int h2 = 0; h2 < 2; ++h2) {
                const int m = by * 128 + wm * 32 + mt * 16 + h2 * 8 + tr;
                float ox = acc[mt][nt][h2*2+0] + b0;
                float oy = acc[mt][nt][h2*2+1] + b1;
                if (MODE == 0) {
                    *(float2*)(Cout + (size_t)m * N + col) = make_float2(ox, oy);
                } else {
                    const int seg = col >> 10;
                    const int c = col & 1023;
                    const int h = c >> 6;
                    const int d = c & 63;
                    const int bb = m >> 10, t = m & 1023;
                    if (seg == 0) { ox *= 0.125f; oy *= 0.125f; }  // fold 1/sqrt(D)
                    uint32_t hw, lw;
                    split2_pack(ox, oy, hw, lw);
                    size_t idx = (((size_t)(bb * H_ + h)) * T_ + t) * D_ + d;
                    __nv_bfloat16 *dh, *dl;
                    if (seg == 0)      { dh = g_Qh; dl = g_Ql; }
                    else if (seg == 1) { dh = g_Kh; dl = g_Kl; }
                    else               { dh = g_Vh; dl = g_Vl; }
                    *(uint32_t*)(dh + idx) = hw;
                    *(uint32_t*)(dl + idx) = lw;
                }
            }
        }
    }
}

// ---------------------------------------------------------------------------
// HMMA flash attention (unchanged from R5)
// ---------------------------------------------------------------------------
#define AST 72
#define QH_OFF 0
#define QL_OFF (128*AST*2)
#define STG0   (2*128*AST*2)
#define KTILE_B (64*AST*2)
#define STG_B  (4*KTILE_B)
#define ASMEM_TOTAL (STG0 + 2*STG_B)   // 110592

__global__ __launch_bounds__(256)
void attn_kernel()
{
    extern __shared__ char smc[];
    const uint32_t sb = smem_u32(smc);
    const int tid = threadIdx.x, wid = tid >> 5, lane = tid & 31;
    const int qt = blockIdx.x, bh = blockIdx.y;
    const int q0 = qt * 128;
    const size_t base = (size_t)bh * T_ * D_;

    {
        const __nv_bfloat16* Qh = g_Qh + base + (size_t)q0 * D_;
        const __nv_bfloat16* Ql = g_Ql + base + (size_t)q0 * D_;
#pragma unroll
        for (int i = 0; i < 4; i++) {
            int idx = tid + i * 256;
            int r = idx >> 3, c = idx & 7;
            cp_async16(sb + QH_OFF + (uint32_t)(r * AST + c * 8) * 2, Qh + (size_t)r * 64 + c * 8);
            cp_async16(sb + QL_OFF + (uint32_t)(r * AST + c * 8) * 2, Ql + (size_t)r * 64 + c * 8);
        }
        CP_COMMIT();
    }

    const int KT = 2 * qt + 2;

    auto load_stage = [&](int st, int kt) {
        const uint32_t s0 = sb + STG0 + st * STG_B;
        const __nv_bfloat16* srcs[4] = {
            g_Kh + base + (size_t)kt * 64 * D_,
            g_Kl + base + (size_t)kt * 64 * D_,
            g_Vh + base + (size_t)kt * 64 * D_,
            g_Vl + base + (size_t)kt * 64 * D_ };
#pragma unroll
        for (int tg = 0; tg < 4; tg++) {
#pragma unroll
            for (int it = 0; it < 2; it++) {
                int r = (tid >> 3) + it * 32, c = tid & 7;
                cp_async16(s0 + tg * KTILE_B + (uint32_t)(r * AST + c * 8) * 2,
                           srcs[tg] + (size_t)r * 64 + c * 8);
            }
        }
    };

    load_stage(0, 0); CP_COMMIT();

    const int a_row = (lane & 7) + ((lane >> 3) & 1) * 8;
    const int a_col = (lane >> 4) * 8;
    const int b_row = (lane & 7) + (lane >> 4) * 8;
    const int b_col = ((lane >> 3) & 1) * 8;
    const int v_row = lane & 15;
    const int v_col = (lane >> 4) * 8;
    const int wm = wid;

    uint32_t qh[4][4], ql[4][4];
    float m_[2] = {-1e30f, -1e30f}, l_[2] = {0.f, 0.f};
    float oacc[8][4];
#pragma unroll
    for (int i = 0; i < 8; i++)
#pragma unroll
        for (int v = 0; v < 4; v++) oacc[i][v] = 0.f;

    const int rbase = q0 + wm * 16;

    for (int kt = 0; kt < KT; ++kt) {
        if (kt + 1 < KT) { load_stage((kt + 1) & 1, kt + 1); CP_COMMIT(); CP_WAIT(1); }
        else             { CP_WAIT(0); }
        __syncthreads();

        if (kt == 0) {
#pragma unroll
            for (int ks = 0; ks < 4; ks++) {
                uint32_t aq = sb + QH_OFF + (uint32_t)((wm * 16 + a_row) * AST + ks * 16 + a_col) * 2;
                ldsm_x4(qh[ks][0], qh[ks][1], qh[ks][2], qh[ks][3], aq);
                ldsm_x4(ql[ks][0], ql[ks][1], ql[ks][2], ql[ks][3], aq + (QL_OFF - QH_OFF));
            }
        }

        const bool active = (kt * 64) <= (rbase + 15);
        if (active) {
            const uint32_t sKh = sb + STG0 + (kt & 1) * STG_B;
            const uint32_t sKl = sKh + KTILE_B;
            const uint32_t sVh = sKh + 2 * KTILE_B;
            const uint32_t sVl = sKh + 3 * KTILE_B;

            float sacc[8][4];
#pragma unroll
            for (int i = 0; i < 8; i++)
#pragma unroll
                for (int v = 0; v < 4; v++) sacc[i][v] = 0.f;

#pragma unroll
            for (int ks = 0; ks < 4; ks++) {
                uint32_t kf[4][4];
#pragma unroll
                for (int np = 0; np < 4; np++) {
                    uint32_t addr = sKh + (uint32_t)((np * 16 + b_row) * AST + ks * 16 + b_col) * 2;
                    ldsm_x4(kf[np][0], kf[np][1], kf[np][2], kf[np][3], addr);
                }
#pragma unroll
                for (int np = 0; np < 4; np++) {
                    mma_bf16(sacc[2*np],   qh[ks][0], qh[ks][1], qh[ks][2], qh[ks][3], kf[np][0], kf[np][1]);
                    mma_bf16(sacc[2*np+1], qh[ks][0], qh[ks][1], qh[ks][2], qh[ks][3], kf[np][2], kf[np][3]);
                    mma_bf16(sacc[2*np],   ql[ks][0], ql[ks][1], ql[ks][2], ql[ks][3], kf[np][0], kf[np][1]);
                    mma_bf16(sacc[2*np+1], ql[ks][0], ql[ks][1], ql[ks][2], ql[ks][3], kf[np][2], kf[np][3]);
                }
#pragma unroll
                for (int np = 0; np < 4; np++) {
                    uint32_t addr = sKl + (uint32_t)((np * 16 + b_row) * AST + ks * 16 + b_col) * 2;
                    ldsm_x4(kf[np][0], kf[np][1], kf[np][2], kf[np][3], addr);
                }
#pragma unroll
                for (int np = 0; np < 4; np++) {
                    mma_bf16(sacc[2*np],   qh[ks][0], qh[ks][1], qh[ks][2], qh[ks][3], kf[np][0], kf[np][1]);
                    mma_bf16(sacc[2*np+1], qh[ks][0], qh[ks][1], qh[ks][2], qh[ks][3], kf[np][2], kf[np][3]);
                }
            }

            if (kt * 64 + 63 > rbase) {
                const int r0r = rbase + (lane >> 2);
#pragma unroll
                for (int nt = 0; nt < 8; nt++) {
#pragma unroll
                    for (int v = 0; v < 4; v++) {
                        int col = kt * 64 + nt * 8 + 2 * (lane & 3) + (v & 1);
                        int row = r0r + (v >> 1) * 8;
                        if (col > row) sacc[nt][v] = -1e30f;
                    }
                }
            }

            float alpha[2];
#pragma unroll
            for (int h2 = 0; h2 < 2; h2++) {
                float mx = -1e30f;
#pragma unroll
                for (int nt = 0; nt < 8; nt++)
                    mx = fmaxf(mx, fmaxf(sacc[nt][2*h2], sacc[nt][2*h2+1]));
                mx = fmaxf(mx, __shfl_xor_sync(0xffffffffu, mx, 1));
                mx = fmaxf(mx, __shfl_xor_sync(0xffffffffu, mx, 2));
                float mnew = fmaxf(m_[h2], mx);
                alpha[h2] = __expf(m_[h2] - mnew);
                float rs = 0.f;
#pragma unroll
                for (int nt = 0; nt < 8; nt++) {
                    sacc[nt][2*h2]   = __expf(sacc[nt][2*h2]   - mnew);
                    sacc[nt][2*h2+1] = __expf(sacc[nt][2*h2+1] - mnew);
                    rs += sacc[nt][2*h2] + sacc[nt][2*h2+1];
                }
                rs += __shfl_xor_sync(0xffffffffu, rs, 1);
                rs += __shfl_xor_sync(0xffffffffu, rs, 2);
                l_[h2] = l_[h2] * alpha[h2] + rs;
                m_[h2] = mnew;
            }
#pragma unroll
            for (int dt = 0; dt < 8; dt++) {
                oacc[dt][0] *= alpha[0]; oacc[dt][1] *= alpha[0];
                oacc[dt][2] *= alpha[1]; oacc[dt][3] *= alpha[1];
            }

#pragma unroll
            for (int ks = 0; ks < 4; ks++) {
                uint32_t ph[4], pl[4];
                split2_pack(sacc[2*ks][0],   sacc[2*ks][1],   ph[0], pl[0]);
                split2_pack(sacc[2*ks][2],   sacc[2*ks][3],   ph[1], pl[1]);
                split2_pack(sacc[2*ks+1][0], sacc[2*ks+1][1], ph[2], pl[2]);
                split2_pack(sacc[2*ks+1][2], sacc[2*ks+1][3], ph[3], pl[3]);

                uint32_t vf[4][4];
#pragma unroll
                for (int nt2 = 0; nt2 < 4; nt2++) {
                    uint32_t addr = sVh + (uint32_t)((ks * 16 + v_row) * AST + nt2 * 16 + v_col) * 2;
                    ldsm_x4_t(vf[nt2][0], vf[nt2][1], vf[nt2][2], vf[nt2][3], addr);
                }
#pragma unroll
                for (int nt2 = 0; nt2 < 4; nt2++) {
                    mma_bf16(oacc[2*nt2],   ph[0], ph[1], ph[2], ph[3], vf[nt2][0], vf[nt2][1]);
                    mma_bf16(oacc[2*nt2+1], ph[0], ph[1], ph[2], ph[3], vf[nt2][2], vf[nt2][3]);
                    mma_bf16(oacc[2*nt2],   pl[0], pl[1], pl[2], pl[3], vf[nt2][0], vf[nt2][1]);
                    mma_bf16(oacc[2*nt2+1], pl[0], pl[1], pl[2], pl[3], vf[nt2][2], vf[nt2][3]);
                }
#pragma unroll
                for (int nt2 = 0; nt2 < 4; nt2++) {
                    uint32_t addr = sVl + (uint32_t)((ks * 16 + v_row) * AST + nt2 * 16 + v_col) * 2;
                    ldsm_x4_t(vf[nt2][0], vf[nt2][1], vf[nt2][2], vf[nt2][3], addr);
                }
#pragma unroll
                for (int nt2 = 0; nt2 < 4; nt2++) {
                    mma_bf16(oacc[2*nt2],   ph[0], ph[1], ph[2], ph[3], vf[nt2][0], vf[nt2][1]);
                    mma_bf16(oacc[2*nt2+1], ph[0], ph[1], ph[2], ph[3], vf[nt2][2], vf[nt2][3]);
                }
            }
        }
        __syncthreads();
    }

    const int bb = bh >> 4, hh = bh & 15;
    const float inv0 = 1.f / l_[0], inv1 = 1.f / l_[1];
#pragma unroll
    for (int dt = 0; dt < 8; dt++) {
#pragma unroll
        for (int h2 = 0; h2 < 2; h2++) {
            const int rloc = wm * 16 + (lane >> 2) + h2 * 8;
            const int d = dt * 8 + 2 * (lane & 3);
            const float inv = h2 ? inv1 : inv0;
            float ox = oacc[dt][2*h2]   * inv;
            float oy = oacc[dt][2*h2+1] * inv;
            uint32_t hw, lw;
            split2_pack(ox, oy, hw, lw);
            const size_t mrow = (size_t)(bb * T_ + q0 + rloc);
            __nv_bfloat16* row = g_Ac + mrow * KE_ + hh * 64 + d;
            *(uint32_t*)(row)          = hw;
            *(uint32_t*)(row + Cc_)    = hw;
            *(uint32_t*)(row + 2*Cc_)  = lw;
        }
    }
}

// ---------------------------------------------------------------------------
extern "C" void kernel_launch(void* const* d_in, const int* in_sizes, int n_in,
                              void* d_out, int out_size)
{
    const float* x    = (const float*)d_in[0];
    const float* Wqkv = (const float*)d_in[1];
    const float* bqkv = (const float*)d_in[2];
    const float* Wout = (const float*)d_in[3];
    const float* bout = (const float*)d_in[4];
    float* out = (float*)d_out;

    cudaFuncSetAttribute(tgemm_kernel<1>,
                         cudaFuncAttributeMaxDynamicSharedMemorySize, GSMEM_TOTAL);
    cudaFuncSetAttribute(tgemm_kernel<0>,
                         cudaFuncAttributeMaxDynamicSharedMemorySize, GSMEM_TOTAL);
    cudaFuncSetAttribute(attn_kernel,
                         cudaFuncAttributeMaxDynamicSharedMemorySize, ASMEM_TOTAL);

    // 0) split conversions
    conv_w<1><<<dim3(Cc_/32, N3_/32), 256>>>(Wqkv, N3_);
    conv_w<0><<<dim3(Cc_/32, Cc_/32), 256>>>(Wout, Cc_);
    conv_act<<<M_*Cc_/4/256, 256>>>(x);

    // 1) QKV projection -> Q/K/V bf16 hi/lo [B,H,T,D] (Q pre-scaled)
    tgemm_kernel<1><<<dim3(N3_/128, M_/128), 256, GSMEM_TOTAL>>>(bqkv, nullptr, N3_);

    // 2) HMMA causal flash attention -> g_Ac (split-expanded)
    attn_kernel<<<dim3(T_/128, BH_), 256, ASMEM_TOTAL>>>();

    // 3) output projection -> d_out
    tgemm_kernel<0><<<dim3(Cc_/128, M_/128), 256, GSMEM_TOTAL>>>(bout, out, Cc_);
}

// round 8
// speedup vs baseline: 1.6640x; 1.5023x over previous
#include <cuda_runtime.h>
#include <cuda_fp16.h>
#include <cstdint>

// Problem constants
#define B_   8
#define T_   1024
#define Cc_  1024
#define H_   16
#define D_   64
#define BH_  (B_*H_)     // 128
#define M_   (B_*T_)     // 8192
#define N3_  3072
#define KA_  (2*Cc_)     // 2048: A' = [hi|lo] fp16
#define KB_  Cc_         // 1024: B rounded fp16 (indexed twice)

// Scratch (static device globals: allocation-free)
__device__ __half g_Qh[(size_t)BH_*T_*D_], g_Ql[(size_t)BH_*T_*D_];
__device__ __half g_Kf[(size_t)BH_*T_*D_];
__device__ __half g_Vf[(size_t)BH_*T_*D_];
__device__ __half g_Ac[(size_t)M_*KA_];      // A' = [hi|lo]
__device__ __half g_Bqkv[(size_t)N3_*KB_];   // B^T rounded fp16
__device__ __half g_Bout[(size_t)Cc_*KB_];

// ---------------------------------------------------------------------------
__device__ __forceinline__ uint32_t smem_u32(const void* p) {
    uint32_t a;
    asm("{ .reg .u64 t; cvta.to.shared.u64 t, %1; cvt.u32.u64 %0, t; }"
        : "=r"(a) : "l"(p));
    return a;
}
__device__ __forceinline__ void ldsm_x4(uint32_t& r0, uint32_t& r1,
                                        uint32_t& r2, uint32_t& r3, uint32_t addr) {
    asm volatile("ldmatrix.sync.aligned.m8n8.x4.shared.b16 {%0,%1,%2,%3}, [%4];"
                 : "=r"(r0), "=r"(r1), "=r"(r2), "=r"(r3) : "r"(addr));
}
__device__ __forceinline__ void ldsm_x4_t(uint32_t& r0, uint32_t& r1,
                                          uint32_t& r2, uint32_t& r3, uint32_t addr) {
    asm volatile("ldmatrix.sync.aligned.m8n8.x4.trans.shared.b16 {%0,%1,%2,%3}, [%4];"
                 : "=r"(r0), "=r"(r1), "=r"(r2), "=r"(r3) : "r"(addr));
}
__device__ __forceinline__ void mma_f16(float* d, uint32_t a0, uint32_t a1,
                                        uint32_t a2, uint32_t a3,
                                        uint32_t b0, uint32_t b1) {
    asm volatile(
        "mma.sync.aligned.m16n8k16.row.col.f32.f16.f16.f32 "
        "{%0,%1,%2,%3}, {%4,%5,%6,%7}, {%8,%9}, {%0,%1,%2,%3};"
        : "+f"(d[0]), "+f"(d[1]), "+f"(d[2]), "+f"(d[3])
        : "r"(a0), "r"(a1), "r"(a2), "r"(a3), "r"(b0), "r"(b1));
}
__device__ __forceinline__ void cp_async16(uint32_t saddr, const void* gaddr) {
    asm volatile("cp.async.cg.shared.global [%0], [%1], 16;"
                 :: "r"(saddr), "l"(gaddr));
}
#define CP_COMMIT() asm volatile("cp.async.commit_group;" ::: "memory")
#define CP_WAIT(n)  asm volatile("cp.async.wait_group %0;" :: "n"(n) : "memory")

__device__ __forceinline__ uint32_t pack_h2(__half a, __half b) {
    return (uint32_t)__half_as_ushort(a) | ((uint32_t)__half_as_ushort(b) << 16);
}
// fp16 split: v = hi + lo (hi = rn(v), lo = rn(v - hi))
__device__ __forceinline__ void split4_h(float4 v, uint2& hi, uint2& lo) {
    float f[4] = {v.x, v.y, v.z, v.w};
    __half h[4], l[4];
#pragma unroll
    for (int i = 0; i < 4; i++) {
        h[i] = __float2half(f[i]);
        l[i] = __float2half(f[i] - __half2float(h[i]));
    }
    hi = make_uint2(pack_h2(h[0], h[1]), pack_h2(h[2], h[3]));
    lo = make_uint2(pack_h2(l[0], l[1]), pack_h2(l[2], l[3]));
}
__device__ __forceinline__ void split2_pack_h(float x, float y, uint32_t& hi, uint32_t& lo) {
    __half hx = __float2half(x), hy = __float2half(y);
    __half lx = __float2half(x - __half2float(hx));
    __half ly = __float2half(y - __half2float(hy));
    hi = pack_h2(hx, hy);
    lo = pack_h2(lx, ly);
}

// ---------------------------------------------------------------------------
// Conversion kernels
// ---------------------------------------------------------------------------
// x [M][1024] fp32 -> g_Ac [M][2048] fp16 [hi | lo]
__global__ __launch_bounds__(256)
void conv_act(const float* __restrict__ src)
{
    int idx = blockIdx.x * 256 + threadIdx.x;
    int m  = idx >> 8;
    int k4 = (idx & 255) << 2;
    float4 v = *(const float4*)(src + (size_t)m * Cc_ + k4);
    uint2 hi, lo;
    split4_h(v, hi, lo);
    __half* drow = g_Ac + (size_t)m * KA_;
    *(uint2*)(drow + k4)       = hi;
    *(uint2*)(drow + Cc_ + k4) = lo;
}

// W [1024][N] fp32 -> Bt [N][1024] fp16 rounded
template<int WSEL>  // 1: g_Bqkv, 0: g_Bout
__global__ __launch_bounds__(256)
void conv_w(const float* __restrict__ W, int N)
{
    __shared__ float tile[32][33];
    __half* Bt = WSEL ? g_Bqkv : g_Bout;
    const int k0 = blockIdx.x * 32, n0 = blockIdx.y * 32;
    const int t = threadIdx.x;
#pragma unroll
    for (int i = 0; i < 4; i++) {
        int r = (t >> 5) + i * 8;
        int c = t & 31;
        tile[r][c] = W[(size_t)(k0 + r) * N + n0 + c];
    }
    __syncthreads();
#pragma unroll
    for (int i = 0; i < 4; i++) {
        int nr = (t >> 5) + i * 8;
        int kc = t & 31;
        Bt[(size_t)(n0 + nr) * KB_ + k0 + kc] = __float2half(tile[kc][nr]);
    }
}

// ---------------------------------------------------------------------------
// Pipelined fp16 HMMA GEMM: 128x128 CTA tile, BK=64, 8 warps (4M x 2N),
// warp tile 32x64, 3-stage cp.async. A over KA_=2048 (32 chunks),
// B chunk = ch & 15 (same 1024-col B serves both A passes).
// MODE 1: epilogue -> Q split fp16 (x0.125) + K/V rounded fp16. MODE 0: fp32.
// ---------------------------------------------------------------------------
#define TSTRIDE 72
#define TILE_B  (128*TSTRIDE*2)
#define STAGE_B (2*TILE_B)
#define NSTAGE  3
#define GSMEM_TOTAL (NSTAGE*STAGE_B)     // 110592
#define NCH     (KA_/64)                 // 32

template<int MODE>
__global__ __launch_bounds__(256)
void tgemm_kernel(const float* __restrict__ bias,
                  float* __restrict__ Cout,
                  int N)
{
    extern __shared__ char smc[];
    const uint32_t sb = smem_u32(smc);
    const int tid = threadIdx.x;
    const int wid = tid >> 5, lane = tid & 31;
    const int bx = blockIdx.x, by = blockIdx.y;
    const int wm = wid & 3;
    const int wn = wid >> 2;

    const __half* Abf = g_Ac + (size_t)(by * 128) * KA_;
    const __half* Bbf = (MODE ? g_Bqkv : g_Bout) + (size_t)(bx * 128) * KB_;

    const int lrow = tid >> 3;
    const int lch  = tid & 7;
    const uint32_t sAoff = (uint32_t)(lrow * TSTRIDE * 2 + lch * 16);

    float acc[2][8][4];
#pragma unroll
    for (int i = 0; i < 2; i++)
#pragma unroll
        for (int j = 0; j < 8; j++)
#pragma unroll
            for (int v = 0; v < 4; v++) acc[i][j][v] = 0.f;

    const int a_row = (lane & 7) + ((lane >> 3) & 1) * 8;
    const int a_col = (lane >> 4) * 8;
    const int b_row = (lane & 7) + (lane >> 4) * 8;
    const int b_col = ((lane >> 3) & 1) * 8;
    const uint32_t aBaseRow = (uint32_t)(wm * 32 + a_row);
    const uint32_t bBaseRow = (uint32_t)(wn * 64 + b_row);

    auto load_stage = [&](int st, int ch) {
        const uint32_t sA = sb + st * STAGE_B + sAoff;
        const uint32_t sB = sA + TILE_B;
        const __half* Ag = Abf + (size_t)lrow * KA_ + ch * 64 + lch * 8;
        const __half* Bg = Bbf + (size_t)lrow * KB_ + (ch & 15) * 64 + lch * 8;
#pragma unroll
        for (int i = 0; i < 4; i++) {
            cp_async16(sA + i * 32 * TSTRIDE * 2, Ag + (size_t)(i * 32) * KA_);
            cp_async16(sB + i * 32 * TSTRIDE * 2, Bg + (size_t)(i * 32) * KB_);
        }
    };

#pragma unroll
    for (int s = 0; s < NSTAGE - 1; ++s) {
        load_stage(s, s);
        CP_COMMIT();
    }

    for (int ch = 0; ch < NCH; ++ch) {
        CP_WAIT(NSTAGE - 2);
        __syncthreads();

        const int lc = ch + NSTAGE - 1;
        if (lc < NCH) load_stage(lc % NSTAGE, lc);
        CP_COMMIT();

        const uint32_t sAp = sb + (ch % NSTAGE) * STAGE_B;
        const uint32_t sBp = sAp + TILE_B;
#pragma unroll
        for (int kk = 0; kk < 4; ++kk) {
            const int kc = kk * 16;
            uint32_t a[2][4];
#pragma unroll
            for (int mt = 0; mt < 2; ++mt) {
                uint32_t addr = sAp + ((aBaseRow + mt * 16) * TSTRIDE + kc + a_col) * 2;
                ldsm_x4(a[mt][0], a[mt][1], a[mt][2], a[mt][3], addr);
            }
            uint32_t b[8][2];
#pragma unroll
            for (int np = 0; np < 4; ++np) {
                uint32_t addr = sBp + ((bBaseRow + np * 16) * TSTRIDE + kc + b_col) * 2;
                uint32_t r0, r1, r2, r3;
                ldsm_x4(r0, r1, r2, r3, addr);
                b[np*2][0] = r0; b[np*2][1] = r1;
                b[np*2+1][0] = r2; b[np*2+1][1] = r3;
            }
#pragma unroll
            for (int mt = 0; mt < 2; ++mt)
#pragma unroll
                for (int nt = 0; nt < 8; ++nt)
                    mma_f16(acc[mt][nt], a[mt][0], a[mt][1], a[mt][2], a[mt][3],
                            b[nt][0], b[nt][1]);
        }
    }

    // -------- epilogue --------
    const int tr = lane >> 2;
    const int tc = (lane & 3) * 2;
#pragma unroll
    for (int mt = 0; mt < 2; ++mt) {
#pragma unroll
        for (int nt = 0; nt < 8; ++nt) {
            const int col = bx * 128 + wn * 64 + nt * 8 + tc;
            const float b0 = __ldg(bias + col);
            const float b1 = __ldg(bias + col + 1);
#pragma unroll
            for (int h2 = 0; h2 < 2; ++h2) {
                const int m = by * 128 + wm * 32 + mt * 16 + h2 * 8 + tr;
                float ox = acc[mt][nt][h2*2+0] + b0;
                float oy = acc[mt][nt][h2*2+1] + b1;
                if (MODE == 0) {
                    *(float2*)(Cout + (size_t)m * N + col) = make_float2(ox, oy);
                } else {
                    const int seg = col >> 10;
                    const int c = col & 1023;
                    const int h = c >> 6;
                    const int d = c & 63;
                    const int bb = m >> 10, t = m & 1023;
                    size_t idx = (((size_t)(bb * H_ + h)) * T_ + t) * D_ + d;
                    if (seg == 0) {
                        ox *= 0.125f; oy *= 0.125f;    // fold 1/sqrt(D)
                        uint32_t hw, lw;
                        split2_pack_h(ox, oy, hw, lw);
                        *(uint32_t*)(g_Qh + idx) = hw;
                        *(uint32_t*)(g_Ql + idx) = lw;
                    } else {
                        uint32_t rw = pack_h2(__float2half(ox), __float2half(oy));
                        *(uint32_t*)(((seg == 1) ? g_Kf : g_Vf) + idx) = rw;
                    }
                }
            }
        }
    }
}

// ---------------------------------------------------------------------------
// HMMA fp16 flash attention: CTA = 128 q-rows x one (b,h). 8 warps, 16 rows
// each. S = Qhi*K + Qlo*K; O += Phi*V + Plo*V. K/V single fp16 tiles,
// double-buffered cp.async. Epilogue -> g_Ac [hi|lo].
// ---------------------------------------------------------------------------
#define AST 72
#define QH_OFF 0
#define QL_OFF (128*AST*2)
#define STG0   (2*128*AST*2)
#define KTILE_B (64*AST*2)
#define STG_B  (2*KTILE_B)
#define ASMEM_TOTAL (STG0 + 2*STG_B)   // 73728

__global__ __launch_bounds__(256)
void attn_kernel()
{
    extern __shared__ char smc[];
    const uint32_t sb = smem_u32(smc);
    const int tid = threadIdx.x, wid = tid >> 5, lane = tid & 31;
    const int qt = blockIdx.x, bh = blockIdx.y;
    const int q0 = qt * 128;
    const size_t base = (size_t)bh * T_ * D_;

    {
        const __half* Qh = g_Qh + base + (size_t)q0 * D_;
        const __half* Ql = g_Ql + base + (size_t)q0 * D_;
#pragma unroll
        for (int i = 0; i < 4; i++) {
            int idx = tid + i * 256;
            int r = idx >> 3, c = idx & 7;
            cp_async16(sb + QH_OFF + (uint32_t)(r * AST + c * 8) * 2, Qh + (size_t)r * 64 + c * 8);
            cp_async16(sb + QL_OFF + (uint32_t)(r * AST + c * 8) * 2, Ql + (size_t)r * 64 + c * 8);
        }
        CP_COMMIT();
    }

    const int KT = 2 * qt + 2;

    auto load_stage = [&](int st, int kt) {
        const uint32_t s0 = sb + STG0 + st * STG_B;
        const __half* srcs[2] = {
            g_Kf + base + (size_t)kt * 64 * D_,
            g_Vf + base + (size_t)kt * 64 * D_ };
#pragma unroll
        for (int tg = 0; tg < 2; tg++) {
#pragma unroll
            for (int it = 0; it < 2; it++) {
                int r = (tid >> 3) + it * 32, c = tid & 7;
                cp_async16(s0 + tg * KTILE_B + (uint32_t)(r * AST + c * 8) * 2,
                           srcs[tg] + (size_t)r * 64 + c * 8);
            }
        }
    };

    load_stage(0, 0); CP_COMMIT();

    const int a_row = (lane & 7) + ((lane >> 3) & 1) * 8;
    const int a_col = (lane >> 4) * 8;
    const int b_row = (lane & 7) + (lane >> 4) * 8;
    const int b_col = ((lane >> 3) & 1) * 8;
    const int v_row = lane & 15;
    const int v_col = (lane >> 4) * 8;
    const int wm = wid;

    uint32_t qh[4][4], ql[4][4];
    float m_[2] = {-1e30f, -1e30f}, l_[2] = {0.f, 0.f};
    float oacc[8][4];
#pragma unroll
    for (int i = 0; i < 8; i++)
#pragma unroll
        for (int v = 0; v < 4; v++) oacc[i][v] = 0.f;

    const int rbase = q0 + wm * 16;

    for (int kt = 0; kt < KT; ++kt) {
        if (kt + 1 < KT) { load_stage((kt + 1) & 1, kt + 1); CP_COMMIT(); CP_WAIT(1); }
        else             { CP_WAIT(0); }
        __syncthreads();

        if (kt == 0) {
#pragma unroll
            for (int ks = 0; ks < 4; ks++) {
                uint32_t aq = sb + QH_OFF + (uint32_t)((wm * 16 + a_row) * AST + ks * 16 + a_col) * 2;
                ldsm_x4(qh[ks][0], qh[ks][1], qh[ks][2], qh[ks][3], aq);
                ldsm_x4(ql[ks][0], ql[ks][1], ql[ks][2], ql[ks][3], aq + (QL_OFF - QH_OFF));
            }
        }

        const bool active = (kt * 64) <= (rbase + 15);
        if (active) {
            const uint32_t sKf = sb + STG0 + (kt & 1) * STG_B;
            const uint32_t sVf = sKf + KTILE_B;

            // ---- S = Qhi*K + Qlo*K ----
            float sacc[8][4];
#pragma unroll
            for (int i = 0; i < 8; i++)
#pragma unroll
                for (int v = 0; v < 4; v++) sacc[i][v] = 0.f;

#pragma unroll
            for (int ks = 0; ks < 4; ks++) {
                uint32_t kf[4][4];
#pragma unroll
                for (int np = 0; np < 4; np++) {
                    uint32_t addr = sKf + (uint32_t)((np * 16 + b_row) * AST + ks * 16 + b_col) * 2;
                    ldsm_x4(kf[np][0], kf[np][1], kf[np][2], kf[np][3], addr);
                }
#pragma unroll
                for (int np = 0; np < 4; np++) {
                    mma_f16(sacc[2*np],   qh[ks][0], qh[ks][1], qh[ks][2], qh[ks][3], kf[np][0], kf[np][1]);
                    mma_f16(sacc[2*np+1], qh[ks][0], qh[ks][1], qh[ks][2], qh[ks][3], kf[np][2], kf[np][3]);
                    mma_f16(sacc[2*np],   ql[ks][0], ql[ks][1], ql[ks][2], ql[ks][3], kf[np][0], kf[np][1]);
                    mma_f16(sacc[2*np+1], ql[ks][0], ql[ks][1], ql[ks][2], ql[ks][3], kf[np][2], kf[np][3]);
                }
            }

            if (kt * 64 + 63 > rbase) {
                const int r0r = rbase + (lane >> 2);
#pragma unroll
                for (int nt = 0; nt < 8; nt++) {
#pragma unroll
                    for (int v = 0; v < 4; v++) {
                        int col = kt * 64 + nt * 8 + 2 * (lane & 3) + (v & 1);
                        int row = r0r + (v >> 1) * 8;
                        if (col > row) sacc[nt][v] = -1e30f;
                    }
                }
            }

            float alpha[2];
#pragma unroll
            for (int h2 = 0; h2 < 2; h2++) {
                float mx = -1e30f;
#pragma unroll
                for (int nt = 0; nt < 8; nt++)
                    mx = fmaxf(mx, fmaxf(sacc[nt][2*h2], sacc[nt][2*h2+1]));
                mx = fmaxf(mx, __shfl_xor_sync(0xffffffffu, mx, 1));
                mx = fmaxf(mx, __shfl_xor_sync(0xffffffffu, mx, 2));
                float mnew = fmaxf(m_[h2], mx);
                alpha[h2] = __expf(m_[h2] - mnew);
                float rs = 0.f;
#pragma unroll
                for (int nt = 0; nt < 8; nt++) {
                    sacc[nt][2*h2]   = __expf(sacc[nt][2*h2]   - mnew);
                    sacc[nt][2*h2+1] = __expf(sacc[nt][2*h2+1] - mnew);
                    rs += sacc[nt][2*h2] + sacc[nt][2*h2+1];
                }
                rs += __shfl_xor_sync(0xffffffffu, rs, 1);
                rs += __shfl_xor_sync(0xffffffffu, rs, 2);
                l_[h2] = l_[h2] * alpha[h2] + rs;
                m_[h2] = mnew;
            }
#pragma unroll
            for (int dt = 0; dt < 8; dt++) {
                oacc[dt][0] *= alpha[0]; oacc[dt][1] *= alpha[0];
                oacc[dt][2] *= alpha[1]; oacc[dt][3] *= alpha[1];
            }

            // ---- O += Phi*V + Plo*V ----
#pragma unroll
            for (int ks = 0; ks < 4; ks++) {
                uint32_t ph[4], pl[4];
                split2_pack_h(sacc[2*ks][0],   sacc[2*ks][1],   ph[0], pl[0]);
                split2_pack_h(sacc[2*ks][2],   sacc[2*ks][3],   ph[1], pl[1]);
                split2_pack_h(sacc[2*ks+1][0], sacc[2*ks+1][1], ph[2], pl[2]);
                split2_pack_h(sacc[2*ks+1][2], sacc[2*ks+1][3], ph[3], pl[3]);

                uint32_t vf[4][4];
#pragma unroll
                for (int nt2 = 0; nt2 < 4; nt2++) {
                    uint32_t addr = sVf + (uint32_t)((ks * 16 + v_row) * AST + nt2 * 16 + v_col) * 2;
                    ldsm_x4_t(vf[nt2][0], vf[nt2][1], vf[nt2][2], vf[nt2][3], addr);
                }
#pragma unroll
                for (int nt2 = 0; nt2 < 4; nt2++) {
                    mma_f16(oacc[2*nt2],   ph[0], ph[1], ph[2], ph[3], vf[nt2][0], vf[nt2][1]);
                    mma_f16(oacc[2*nt2+1], ph[0], ph[1], ph[2], ph[3], vf[nt2][2], vf[nt2][3]);
                    mma_f16(oacc[2*nt2],   pl[0], pl[1], pl[2], pl[3], vf[nt2][0], vf[nt2][1]);
                    mma_f16(oacc[2*nt2+1], pl[0], pl[1], pl[2], pl[3], vf[nt2][2], vf[nt2][3]);
                }
            }
        }
        __syncthreads();
    }

    // ---- epilogue: O/l -> g_Ac [hi|lo] ----
    const int bb = bh >> 4, hh = bh & 15;
    const float inv0 = 1.f / l_[0], inv1 = 1.f / l_[1];
#pragma unroll
    for (int dt = 0; dt < 8; dt++) {
#pragma unroll
        for (int h2 = 0; h2 < 2; h2++) {
            const int rloc = wm * 16 + (lane >> 2) + h2 * 8;
            const int d = dt * 8 + 2 * (lane & 3);
            const float inv = h2 ? inv1 : inv0;
            float ox = oacc[dt][2*h2]   * inv;
            float oy = oacc[dt][2*h2+1] * inv;
            uint32_t hw, lw;
            split2_pack_h(ox, oy, hw, lw);
            const size_t mrow = (size_t)(bb * T_ + q0 + rloc);
            __half* row = g_Ac + mrow * KA_ + hh * 64 + d;
            *(uint32_t*)(row)       = hw;
            *(uint32_t*)(row + Cc_) = lw;
        }
    }
}

// ---------------------------------------------------------------------------
extern "C" void kernel_launch(void* const* d_in, const int* in_sizes, int n_in,
                              void* d_out, int out_size)
{
    const float* x    = (const float*)d_in[0];
    const float* Wqkv = (const float*)d_in[1];
    const float* bqkv = (const float*)d_in[2];
    const float* Wout = (const float*)d_in[3];
    const float* bout = (const float*)d_in[4];
    float* out = (float*)d_out;

    cudaFuncSetAttribute(tgemm_kernel<1>,
                         cudaFuncAttributeMaxDynamicSharedMemorySize, GSMEM_TOTAL);
    cudaFuncSetAttribute(tgemm_kernel<0>,
                         cudaFuncAttributeMaxDynamicSharedMemorySize, GSMEM_TOTAL);
    cudaFuncSetAttribute(attn_kernel,
                         cudaFuncAttributeMaxDynamicSharedMemorySize, ASMEM_TOTAL);

    // 0) conversions (fp16: split x, round W)
    conv_w<1><<<dim3(Cc_/32, N3_/32), 256>>>(Wqkv, N3_);
    conv_w<0><<<dim3(Cc_/32, Cc_/32), 256>>>(Wout, Cc_);
    conv_act<<<M_*Cc_/4/256, 256>>>(x);

    // 1) QKV projection -> Q split fp16 (x0.125) + K/V rounded fp16 [B,H,T,D]
    tgemm_kernel<1><<<dim3(N3_/128, M_/128), 256, GSMEM_TOTAL>>>(bqkv, nullptr, N3_);

    // 2) fp16 HMMA causal flash attention -> g_Ac [hi|lo]
    attn_kernel<<<dim3(T_/128, BH_), 256, ASMEM_TOTAL>>>();

    // 3) output projection -> d_out
    tgemm_kernel<0><<<dim3(Cc_/128, M_/128), 256, GSMEM_TOTAL>>>(bout, out, Cc_);
}

// round 9
// speedup vs baseline: 1.9655x; 1.1812x over previous
#include <cuda_runtime.h>
#include <cuda_fp16.h>
#include <cstdint>

// Problem constants
#define B_   8
#define T_   1024
#define Cc_  1024
#define H_   16
#define D_   64
#define BH_  (B_*H_)     // 128
#define M_   (B_*T_)     // 8192
#define N3_  3072
#define KA_  (2*Cc_)     // 2048: A' = [hi|lo] fp16
#define KB_  Cc_         // 1024: B rounded fp16

// Scratch (static device globals: allocation-free)
__device__ __half g_Qh[(size_t)BH_*T_*D_], g_Ql[(size_t)BH_*T_*D_];
__device__ __half g_Kf[(size_t)BH_*T_*D_];
__device__ __half g_Vf[(size_t)BH_*T_*D_];
__device__ __half g_Ac[(size_t)M_*KA_];      // A' = [hi|lo]
__device__ __half g_Bqkv[(size_t)N3_*KB_];
__device__ __half g_Bout[(size_t)Cc_*KB_];

// ---------------------------------------------------------------------------
__device__ __forceinline__ uint32_t smem_u32(const void* p) {
    uint32_t a;
    asm("{ .reg .u64 t; cvta.to.shared.u64 t, %1; cvt.u32.u64 %0, t; }"
        : "=r"(a) : "l"(p));
    return a;
}
__device__ __forceinline__ void ldsm_x4(uint32_t& r0, uint32_t& r1,
                                        uint32_t& r2, uint32_t& r3, uint32_t addr) {
    asm volatile("ldmatrix.sync.aligned.m8n8.x4.shared.b16 {%0,%1,%2,%3}, [%4];"
                 : "=r"(r0), "=r"(r1), "=r"(r2), "=r"(r3) : "r"(addr));
}
__device__ __forceinline__ void ldsm_x4_t(uint32_t& r0, uint32_t& r1,
                                          uint32_t& r2, uint32_t& r3, uint32_t addr) {
    asm volatile("ldmatrix.sync.aligned.m8n8.x4.trans.shared.b16 {%0,%1,%2,%3}, [%4];"
                 : "=r"(r0), "=r"(r1), "=r"(r2), "=r"(r3) : "r"(addr));
}
__device__ __forceinline__ void mma_f16(float* d, uint32_t a0, uint32_t a1,
                                        uint32_t a2, uint32_t a3,
                                        uint32_t b0, uint32_t b1) {
    asm volatile(
        "mma.sync.aligned.m16n8k16.row.col.f32.f16.f16.f32 "
        "{%0,%1,%2,%3}, {%4,%5,%6,%7}, {%8,%9}, {%0,%1,%2,%3};"
        : "+f"(d[0]), "+f"(d[1]), "+f"(d[2]), "+f"(d[3])
        : "r"(a0), "r"(a1), "r"(a2), "r"(a3), "r"(b0), "r"(b1));
}
__device__ __forceinline__ void cp_async16(uint32_t saddr, const void* gaddr) {
    asm volatile("cp.async.cg.shared.global [%0], [%1], 16;"
                 :: "r"(saddr), "l"(gaddr));
}
#define CP_COMMIT() asm volatile("cp.async.commit_group;" ::: "memory")
#define CP_WAIT(n)  asm volatile("cp.async.wait_group %0;" :: "n"(n) : "memory")

__device__ __forceinline__ uint32_t pack_h2(__half a, __half b) {
    return (uint32_t)__half_as_ushort(a) | ((uint32_t)__half_as_ushort(b) << 16);
}
__device__ __forceinline__ void split4_h(float4 v, uint2& hi, uint2& lo) {
    float f[4] = {v.x, v.y, v.z, v.w};
    __half h[4], l[4];
#pragma unroll
    for (int i = 0; i < 4; i++) {
        h[i] = __float2half(f[i]);
        l[i] = __float2half(f[i] - __half2float(h[i]));
    }
    hi = make_uint2(pack_h2(h[0], h[1]), pack_h2(h[2], h[3]));
    lo = make_uint2(pack_h2(l[0], l[1]), pack_h2(l[2], l[3]));
}
__device__ __forceinline__ void split2_pack_h(float x, float y, uint32_t& hi, uint32_t& lo) {
    __half hx = __float2half(x), hy = __float2half(y);
    __half lx = __float2half(x - __half2float(hx));
    __half ly = __float2half(y - __half2float(hy));
    hi = pack_h2(hx, hy);
    lo = pack_h2(lx, ly);
}

// ---------------------------------------------------------------------------
// Conversion kernels
// ---------------------------------------------------------------------------
__global__ __launch_bounds__(256)
void conv_act(const float* __restrict__ src)
{
    int idx = blockIdx.x * 256 + threadIdx.x;
    int m  = idx >> 8;
    int k4 = (idx & 255) << 2;
    float4 v = *(const float4*)(src + (size_t)m * Cc_ + k4);
    uint2 hi, lo;
    split4_h(v, hi, lo);
    __half* drow = g_Ac + (size_t)m * KA_;
    *(uint2*)(drow + k4)       = hi;
    *(uint2*)(drow + Cc_ + k4) = lo;
}

template<int WSEL>
__global__ __launch_bounds__(256)
void conv_w(const float* __restrict__ W, int N)
{
    __shared__ float tile[32][33];
    __half* Bt = WSEL ? g_Bqkv : g_Bout;
    const int k0 = blockIdx.x * 32, n0 = blockIdx.y * 32;
    const int t = threadIdx.x;
#pragma unroll
    for (int i = 0; i < 4; i++) {
        int r = (t >> 5) + i * 8;
        int c = t & 31;
        tile[r][c] = W[(size_t)(k0 + r) * N + n0 + c];
    }
    __syncthreads();
#pragma unroll
    for (int i = 0; i < 4; i++) {
        int nr = (t >> 5) + i * 8;
        int kc = t & 31;
        Bt[(size_t)(n0 + nr) * KB_ + k0 + kc] = __float2half(tile[kc][nr]);
    }
}

// ---------------------------------------------------------------------------
// Pipelined fp16 HMMA GEMM, fused two-pass: 128x128 CTA tile, BK=64, 8 warps
// (4M x 2N, warp 32x64). Stage = {A_hi, A_lo, B}; B fragments loaded once per
// kk and used against both A_hi and A_lo. 2-stage cp.async. 16 B-chunks.
// MODE 1: K/V tiles (bx>=8) single-pass (A_hi only); epilogue -> Q split fp16
// (x0.125), K/V rounded fp16. MODE 0: always two-pass, fp32 out.
// ---------------------------------------------------------------------------
#define TSTRIDE 72
#define TILE_B  (128*TSTRIDE*2)          // 18432
#define STAGE_B (3*TILE_B)               // A_hi + A_lo + B = 55296
#define NSTAGE  2
#define GSMEM_TOTAL (NSTAGE*STAGE_B)     // 110592
#define NCHB    (KB_/64)                 // 16

template<int MODE>
__global__ __launch_bounds__(256)
void tgemm_kernel(const float* __restrict__ bias,
                  float* __restrict__ Cout,
                  int N)
{
    extern __shared__ char smc[];
    const uint32_t sb = smem_u32(smc);
    const int tid = threadIdx.x;
    const int wid = tid >> 5, lane = tid & 31;
    const int bx = blockIdx.x, by = blockIdx.y;
    const int wm = wid & 3;
    const int wn = wid >> 2;
    const bool twopass = (MODE == 0) || (bx < 8);   // Q tiles two-pass; K/V single

    const __half* Abf = g_Ac + (size_t)(by * 128) * KA_;
    const __half* Bbf = (MODE ? g_Bqkv : g_Bout) + (size_t)(bx * 128) * KB_;

    const int lrow = tid >> 3;
    const int lch  = tid & 7;
    const uint32_t sOff = (uint32_t)(lrow * TSTRIDE * 2 + lch * 16);

    float acc[2][8][4];
#pragma unroll
    for (int i = 0; i < 2; i++)
#pragma unroll
        for (int j = 0; j < 8; j++)
#pragma unroll
            for (int v = 0; v < 4; v++) acc[i][j][v] = 0.f;

    const int a_row = (lane & 7) + ((lane >> 3) & 1) * 8;
    const int a_col = (lane >> 4) * 8;
    const int b_row = (lane & 7) + (lane >> 4) * 8;
    const int b_col = ((lane >> 3) & 1) * 8;
    const uint32_t aBaseRow = (uint32_t)(wm * 32 + a_row);
    const uint32_t bBaseRow = (uint32_t)(wn * 64 + b_row);

    auto load_stage = [&](int st, int ch) {
        const uint32_t sAh = sb + st * STAGE_B + sOff;
        const uint32_t sAl = sAh + TILE_B;
        const uint32_t sB  = sAh + 2 * TILE_B;
        const __half* Ag = Abf + (size_t)lrow * KA_ + ch * 64 + lch * 8;
        const __half* Bg = Bbf + (size_t)lrow * KB_ + ch * 64 + lch * 8;
#pragma unroll
        for (int i = 0; i < 4; i++) {
            cp_async16(sAh + i * 32 * TSTRIDE * 2, Ag + (size_t)(i * 32) * KA_);
            cp_async16(sB  + i * 32 * TSTRIDE * 2, Bg + (size_t)(i * 32) * KB_);
        }
        if (twopass) {
#pragma unroll
            for (int i = 0; i < 4; i++)
                cp_async16(sAl + i * 32 * TSTRIDE * 2,
                           Ag + Cc_ + (size_t)(i * 32) * KA_);
        }
    };

    load_stage(0, 0);
    CP_COMMIT();

    for (int ch = 0; ch < NCHB; ++ch) {
        if (ch + 1 < NCHB) { load_stage((ch + 1) & 1, ch + 1); CP_COMMIT(); CP_WAIT(1); }
        else               { CP_WAIT(0); }
        __syncthreads();

        const uint32_t sAh = sb + (ch & 1) * STAGE_B;
        const uint32_t sAl = sAh + TILE_B;
        const uint32_t sBp = sAh + 2 * TILE_B;
#pragma unroll
        for (int kk = 0; kk < 4; ++kk) {
            const int kc = kk * 16;
            uint32_t b[8][2];
#pragma unroll
            for (int np = 0; np < 4; ++np) {
                uint32_t addr = sBp + ((bBaseRow + np * 16) * TSTRIDE + kc + b_col) * 2;
                uint32_t r0, r1, r2, r3;
                ldsm_x4(r0, r1, r2, r3, addr);
                b[np*2][0] = r0; b[np*2][1] = r1;
                b[np*2+1][0] = r2; b[np*2+1][1] = r3;
            }
            uint32_t a[2][4];
#pragma unroll
            for (int mt = 0; mt < 2; ++mt) {
                uint32_t addr = sAh + ((aBaseRow + mt * 16) * TSTRIDE + kc + a_col) * 2;
                ldsm_x4(a[mt][0], a[mt][1], a[mt][2], a[mt][3], addr);
            }
#pragma unroll
            for (int mt = 0; mt < 2; ++mt)
#pragma unroll
                for (int nt = 0; nt < 8; ++nt)
                    mma_f16(acc[mt][nt], a[mt][0], a[mt][1], a[mt][2], a[mt][3],
                            b[nt][0], b[nt][1]);
            if (twopass) {
#pragma unroll
                for (int mt = 0; mt < 2; ++mt) {
                    uint32_t addr = sAl + ((aBaseRow + mt * 16) * TSTRIDE + kc + a_col) * 2;
                    ldsm_x4(a[mt][0], a[mt][1], a[mt][2], a[mt][3], addr);
                }
#pragma unroll
                for (int mt = 0; mt < 2; ++mt)
#pragma unroll
                    for (int nt = 0; nt < 8; ++nt)
                        mma_f16(acc[mt][nt], a[mt][0], a[mt][1], a[mt][2], a[mt][3],
                                b[nt][0], b[nt][1]);
            }
        }
        __syncthreads();   // all reads of this stage done before next load overwrites
    }

    // -------- epilogue --------
    const int tr = lane >> 2;
    const int tc = (lane & 3) * 2;
#pragma unroll
    for (int mt = 0; mt < 2; ++mt) {
#pragma unroll
        for (int nt = 0; nt < 8; ++nt) {
            const int col = bx * 128 + wn * 64 + nt * 8 + tc;
            const float b0 = __ldg(bias + col);
            const float b1 = __ldg(bias + col + 1);
#pragma unroll
            for (int h2 = 0; h2 < 2; ++h2) {
                const int m = by * 128 + wm * 32 + mt * 16 + h2 * 8 + tr;
                float ox = acc[mt][nt][h2*2+0] + b0;
                float oy = acc[mt][nt][h2*2+1] + b1;
                if (MODE == 0) {
                    *(float2*)(Cout + (size_t)m * N + col) = make_float2(ox, oy);
                } else {
                    const int seg = col >> 10;
                    const int c = col & 1023;
                    const int h = c >> 6;
                    const int d = c & 63;
                    const int bb = m >> 10, t = m & 1023;
                    size_t idx = (((size_t)(bb * H_ + h)) * T_ + t) * D_ + d;
                    if (seg == 0) {
                        ox *= 0.125f; oy *= 0.125f;
                        uint32_t hw, lw;
                        split2_pack_h(ox, oy, hw, lw);
                        *(uint32_t*)(g_Qh + idx) = hw;
                        *(uint32_t*)(g_Ql + idx) = lw;
                    } else {
                        uint32_t rw = pack_h2(__float2half(ox), __float2half(oy));
                        *(uint32_t*)(((seg == 1) ? g_Kf : g_Vf) + idx) = rw;
                    }
                }
            }
        }
    }
}

// ---------------------------------------------------------------------------
// HMMA fp16 flash attention (R8, + heavy-tiles-first ordering)
// ---------------------------------------------------------------------------
#define AST 72
#define QH_OFF 0
#define QL_OFF (128*AST*2)
#define STG0   (2*128*AST*2)
#define KTILE_B (64*AST*2)
#define STG_B  (2*KTILE_B)
#define ASMEM_TOTAL (STG0 + 2*STG_B)   // 73728

__global__ __launch_bounds__(256)
void attn_kernel()
{
    extern __shared__ char smc[];
    const uint32_t sb = smem_u32(smc);
    const int tid = threadIdx.x, wid = tid >> 5, lane = tid & 31;
    const int qt = gridDim.x - 1 - blockIdx.x;   // heavy tiles first
    const int bh = blockIdx.y;
    const int q0 = qt * 128;
    const size_t base = (size_t)bh * T_ * D_;

    {
        const __half* Qh = g_Qh + base + (size_t)q0 * D_;
        const __half* Ql = g_Ql + base + (size_t)q0 * D_;
#pragma unroll
        for (int i = 0; i < 4; i++) {
            int idx = tid + i * 256;
            int r = idx >> 3, c = idx & 7;
            cp_async16(sb + QH_OFF + (uint32_t)(r * AST + c * 8) * 2, Qh + (size_t)r * 64 + c * 8);
            cp_async16(sb + QL_OFF + (uint32_t)(r * AST + c * 8) * 2, Ql + (size_t)r * 64 + c * 8);
        }
        CP_COMMIT();
    }

    const int KT = 2 * qt + 2;

    auto load_stage = [&](int st, int kt) {
        const uint32_t s0 = sb + STG0 + st * STG_B;
        const __half* srcs[2] = {
            g_Kf + base + (size_t)kt * 64 * D_,
            g_Vf + base + (size_t)kt * 64 * D_ };
#pragma unroll
        for (int tg = 0; tg < 2; tg++) {
#pragma unroll
            for (int it = 0; it < 2; it++) {
                int r = (tid >> 3) + it * 32, c = tid & 7;
                cp_async16(s0 + tg * KTILE_B + (uint32_t)(r * AST + c * 8) * 2,
                           srcs[tg] + (size_t)r * 64 + c * 8);
            }
        }
    };

    load_stage(0, 0); CP_COMMIT();

    const int a_row = (lane & 7) + ((lane >> 3) & 1) * 8;
    const int a_col = (lane >> 4) * 8;
    const int b_row = (lane & 7) + (lane >> 4) * 8;
    const int b_col = ((lane >> 3) & 1) * 8;
    const int v_row = lane & 15;
    const int v_col = (lane >> 4) * 8;
    const int wm = wid;

    uint32_t qh[4][4], ql[4][4];
    float m_[2] = {-1e30f, -1e30f}, l_[2] = {0.f, 0.f};
    float oacc[8][4];
#pragma unroll
    for (int i = 0; i < 8; i++)
#pragma unroll
        for (int v = 0; v < 4; v++) oacc[i][v] = 0.f;

    const int rbase = q0 + wm * 16;

    for (int kt = 0; kt < KT; ++kt) {
        if (kt + 1 < KT) { load_stage((kt + 1) & 1, kt + 1); CP_COMMIT(); CP_WAIT(1); }
        else             { CP_WAIT(0); }
        __syncthreads();

        if (kt == 0) {
#pragma unroll
            for (int ks = 0; ks < 4; ks++) {
                uint32_t aq = sb + QH_OFF + (uint32_t)((wm * 16 + a_row) * AST + ks * 16 + a_col) * 2;
                ldsm_x4(qh[ks][0], qh[ks][1], qh[ks][2], qh[ks][3], aq);
                ldsm_x4(ql[ks][0], ql[ks][1], ql[ks][2], ql[ks][3], aq + (QL_OFF - QH_OFF));
            }
        }

        const bool active = (kt * 64) <= (rbase + 15);
        if (active) {
            const uint32_t sKf = sb + STG0 + (kt & 1) * STG_B;
            const uint32_t sVf = sKf + KTILE_B;

            float sacc[8][4];
#pragma unroll
            for (int i = 0; i < 8; i++)
#pragma unroll
                for (int v = 0; v < 4; v++) sacc[i][v] = 0.f;

#pragma unroll
            for (int ks = 0; ks < 4; ks++) {
                uint32_t kf[4][4];
#pragma unroll
                for (int np = 0; np < 4; np++) {
                    uint32_t addr = sKf + (uint32_t)((np * 16 + b_row) * AST + ks * 16 + b_col) * 2;
                    ldsm_x4(kf[np][0], kf[np][1], kf[np][2], kf[np][3], addr);
                }
#pragma unroll
                for (int np = 0; np < 4; np++) {
                    mma_f16(sacc[2*np],   qh[ks][0], qh[ks][1], qh[ks][2], qh[ks][3], kf[np][0], kf[np][1]);
                    mma_f16(sacc[2*np+1], qh[ks][0], qh[ks][1], qh[ks][2], qh[ks][3], kf[np][2], kf[np][3]);
                    mma_f16(sacc[2*np],   ql[ks][0], ql[ks][1], ql[ks][2], ql[ks][3], kf[np][0], kf[np][1]);
                    mma_f16(sacc[2*np+1], ql[ks][0], ql[ks][1], ql[ks][2], ql[ks][3], kf[np][2], kf[np][3]);
                }
            }

            if (kt * 64 + 63 > rbase) {
                const int r0r = rbase + (lane >> 2);
#pragma unroll
                for (int nt = 0; nt < 8; nt++) {
#pragma unroll
                    for (int v = 0; v < 4; v++) {
                        int col = kt * 64 + nt * 8 + 2 * (lane & 3) + (v & 1);
                        int row = r0r + (v >> 1) * 8;
                        if (col > row) sacc[nt][v] = -1e30f;
                    }
                }
            }

            float alpha[2];
#pragma unroll
            for (int h2 = 0; h2 < 2; h2++) {
                float mx = -1e30f;
#pragma unroll
                for (int nt = 0; nt < 8; nt++)
                    mx = fmaxf(mx, fmaxf(sacc[nt][2*h2], sacc[nt][2*h2+1]));
                mx = fmaxf(mx, __shfl_xor_sync(0xffffffffu, mx, 1));
                mx = fmaxf(mx, __shfl_xor_sync(0xffffffffu, mx, 2));
                float mnew = fmaxf(m_[h2], mx);
                alpha[h2] = __expf(m_[h2] - mnew);
                float rs = 0.f;
#pragma unroll
                for (int nt = 0; nt < 8; nt++) {
                    sacc[nt][2*h2]   = __expf(sacc[nt][2*h2]   - mnew);
                    sacc[nt][2*h2+1] = __expf(sacc[nt][2*h2+1] - mnew);
                    rs += sacc[nt][2*h2] + sacc[nt][2*h2+1];
                }
                rs += __shfl_xor_sync(0xffffffffu, rs, 1);
                rs += __shfl_xor_sync(0xffffffffu, rs, 2);
                l_[h2] = l_[h2] * alpha[h2] + rs;
                m_[h2] = mnew;
            }
#pragma unroll
            for (int dt = 0; dt < 8; dt++) {
                oacc[dt][0] *= alpha[0]; oacc[dt][1] *= alpha[0];
                oacc[dt][2] *= alpha[1]; oacc[dt][3] *= alpha[1];
            }

#pragma unroll
            for (int ks = 0; ks < 4; ks++) {
                uint32_t ph[4], pl[4];
                split2_pack_h(sacc[2*ks][0],   sacc[2*ks][1],   ph[0], pl[0]);
                split2_pack_h(sacc[2*ks][2],   sacc[2*ks][3],   ph[1], pl[1]);
                split2_pack_h(sacc[2*ks+1][0], sacc[2*ks+1][1], ph[2], pl[2]);
                split2_pack_h(sacc[2*ks+1][2], sacc[2*ks+1][3], ph[3], pl[3]);

                uint32_t vf[4][4];
#pragma unroll
                for (int nt2 = 0; nt2 < 4; nt2++) {
                    uint32_t addr = sVf + (uint32_t)((ks * 16 + v_row) * AST + nt2 * 16 + v_col) * 2;
                    ldsm_x4_t(vf[nt2][0], vf[nt2][1], vf[nt2][2], vf[nt2][3], addr);
                }
#pragma unroll
                for (int nt2 = 0; nt2 < 4; nt2++) {
                    mma_f16(oacc[2*nt2],   ph[0], ph[1], ph[2], ph[3], vf[nt2][0], vf[nt2][1]);
                    mma_f16(oacc[2*nt2+1], ph[0], ph[1], ph[2], ph[3], vf[nt2][2], vf[nt2][3]);
                    mma_f16(oacc[2*nt2],   pl[0], pl[1], pl[2], pl[3], vf[nt2][0], vf[nt2][1]);
                    mma_f16(oacc[2*nt2+1], pl[0], pl[1], pl[2], pl[3], vf[nt2][2], vf[nt2][3]);
                }
            }
        }
        __syncthreads();
    }

    const int bb = bh >> 4, hh = bh & 15;
    const float inv0 = 1.f / l_[0], inv1 = 1.f / l_[1];
#pragma unroll
    for (int dt = 0; dt < 8; dt++) {
#pragma unroll
        for (int h2 = 0; h2 < 2; h2++) {
            const int rloc = wm * 16 + (lane >> 2) + h2 * 8;
            const int d = dt * 8 + 2 * (lane & 3);
            const float inv = h2 ? inv1 : inv0;
            float ox = oacc[dt][2*h2]   * inv;
            float oy = oacc[dt][2*h2+1] * inv;
            uint32_t hw, lw;
            split2_pack_h(ox, oy, hw, lw);
            const size_t mrow = (size_t)(bb * T_ + q0 + rloc);
            __half* row = g_Ac + mrow * KA_ + hh * 64 + d;
            *(uint32_t*)(row)       = hw;
            *(uint32_t*)(row + Cc_) = lw;
        }
    }
}

// ---------------------------------------------------------------------------
extern "C" void kernel_launch(void* const* d_in, const int* in_sizes, int n_in,
                              void* d_out, int out_size)
{
    const float* x    = (const float*)d_in[0];
    const float* Wqkv = (const float*)d_in[1];
    const float* bqkv = (const float*)d_in[2];
    const float* Wout = (const float*)d_in[3];
    const float* bout = (const float*)d_in[4];
    float* out = (float*)d_out;

    cudaFuncSetAttribute(tgemm_kernel<1>,
                         cudaFuncAttributeMaxDynamicSharedMemorySize, GSMEM_TOTAL);
    cudaFuncSetAttribute(tgemm_kernel<0>,
                         cudaFuncAttributeMaxDynamicSharedMemorySize, GSMEM_TOTAL);
    cudaFuncSetAttribute(attn_kernel,
                         cudaFuncAttributeMaxDynamicSharedMemorySize, ASMEM_TOTAL);

    // 0) conversions (fp16: split x, round W)
    conv_w<1><<<dim3(Cc_/32, N3_/32), 256>>>(Wqkv, N3_);
    conv_w<0><<<dim3(Cc_/32, Cc_/32), 256>>>(Wout, Cc_);
    conv_act<<<M_*Cc_/4/256, 256>>>(x);

    // 1) QKV projection (fused 2-pass; K/V tiles single-pass)
    tgemm_kernel<1><<<dim3(N3_/128, M_/128), 256, GSMEM_TOTAL>>>(bqkv, nullptr, N3_);

    // 2) fp16 HMMA causal flash attention -> g_Ac [hi|lo]
    attn_kernel<<<dim3(T_/128, BH_), 256, ASMEM_TOTAL>>>();

    // 3) output projection -> d_out
    tgemm_kernel<0><<<dim3(Cc_/128, M_/128), 256, GSMEM_TOTAL>>>(bout, out, Cc_);
}

// round 10
// speedup vs baseline: 2.9646x; 1.5083x over previous
#include <cuda_runtime.h>
#include <cuda_fp16.h>
#include <cstdint>

// Problem constants
#define B_   8
#define T_   1024
#define Cc_  1024
#define H_   16
#define D_   64
#define BH_  (B_*H_)     // 128
#define M_   (B_*T_)     // 8192
#define N3_  3072
#define KB_  Cc_         // 1024

// Scratch (static device globals: allocation-free)
__device__ __half g_Qf[(size_t)BH_*T_*D_];
__device__ __half g_Kf[(size_t)BH_*T_*D_];
__device__ __half g_Vf[(size_t)BH_*T_*D_];
__device__ __half g_A[(size_t)M_*Cc_];       // acts fp16: x for QKV, then O for proj
__device__ __half g_Bqkv[(size_t)N3_*KB_];
__device__ __half g_Bout[(size_t)Cc_*KB_];

// ---------------------------------------------------------------------------
__device__ __forceinline__ uint32_t smem_u32(const void* p) {
    uint32_t a;
    asm("{ .reg .u64 t; cvta.to.shared.u64 t, %1; cvt.u32.u64 %0, t; }"
        : "=r"(a) : "l"(p));
    return a;
}
__device__ __forceinline__ void ldsm_x4(uint32_t& r0, uint32_t& r1,
                                        uint32_t& r2, uint32_t& r3, uint32_t addr) {
    asm volatile("ldmatrix.sync.aligned.m8n8.x4.shared.b16 {%0,%1,%2,%3}, [%4];"
                 : "=r"(r0), "=r"(r1), "=r"(r2), "=r"(r3) : "r"(addr));
}
__device__ __forceinline__ void ldsm_x4_t(uint32_t& r0, uint32_t& r1,
                                          uint32_t& r2, uint32_t& r3, uint32_t addr) {
    asm volatile("ldmatrix.sync.aligned.m8n8.x4.trans.shared.b16 {%0,%1,%2,%3}, [%4];"
                 : "=r"(r0), "=r"(r1), "=r"(r2), "=r"(r3) : "r"(addr));
}
__device__ __forceinline__ void mma_f16(float* d, uint32_t a0, uint32_t a1,
                                        uint32_t a2, uint32_t a3,
                                        uint32_t b0, uint32_t b1) {
    asm volatile(
        "mma.sync.aligned.m16n8k16.row.col.f32.f16.f16.f32 "
        "{%0,%1,%2,%3}, {%4,%5,%6,%7}, {%8,%9}, {%0,%1,%2,%3};"
        : "+f"(d[0]), "+f"(d[1]), "+f"(d[2]), "+f"(d[3])
        : "r"(a0), "r"(a1), "r"(a2), "r"(a3), "r"(b0), "r"(b1));
}
__device__ __forceinline__ void cp_async16(uint32_t saddr, const void* gaddr) {
    asm volatile("cp.async.cg.shared.global [%0], [%1], 16;"
                 :: "r"(saddr), "l"(gaddr));
}
#define CP_COMMIT() asm volatile("cp.async.commit_group;" ::: "memory")
#define CP_WAIT(n)  asm volatile("cp.async.wait_group %0;" :: "n"(n) : "memory")

__device__ __forceinline__ uint32_t pack_h2(__half a, __half b) {
    return (uint32_t)__half_as_ushort(a) | ((uint32_t)__half_as_ushort(b) << 16);
}

// ---------------------------------------------------------------------------
// Conversion kernels (round to fp16)
// ---------------------------------------------------------------------------
__global__ __launch_bounds__(256)
void conv_act(const float* __restrict__ src)
{
    int idx = blockIdx.x * 256 + threadIdx.x;
    int m  = idx >> 8;
    int k4 = (idx & 255) << 2;
    float4 v = *(const float4*)(src + (size_t)m * Cc_ + k4);
    uint2 w = make_uint2(pack_h2(__float2half(v.x), __float2half(v.y)),
                         pack_h2(__float2half(v.z), __float2half(v.w)));
    *(uint2*)(g_A + (size_t)m * Cc_ + k4) = w;
}

template<int WSEL>
__global__ __launch_bounds__(256)
void conv_w(const float* __restrict__ W, int N)
{
    __shared__ float tile[32][33];
    __half* Bt = WSEL ? g_Bqkv : g_Bout;
    const int k0 = blockIdx.x * 32, n0 = blockIdx.y * 32;
    const int t = threadIdx.x;
#pragma unroll
    for (int i = 0; i < 4; i++) {
        int r = (t >> 5) + i * 8;
        int c = t & 31;
        tile[r][c] = W[(size_t)(k0 + r) * N + n0 + c];
    }
    __syncthreads();
#pragma unroll
    for (int i = 0; i < 4; i++) {
        int nr = (t >> 5) + i * 8;
        int kc = t & 31;
        Bt[(size_t)(n0 + nr) * KB_ + k0 + kc] = __float2half(tile[kc][nr]);
    }
}

// ---------------------------------------------------------------------------
// Pipelined fp16 HMMA GEMM (single-pass): 128x128 CTA tile, BK=64, 8 warps
// (4M x 2N, warp 32x64), 3-stage cp.async, one barrier per chunk. K=1024.
// MODE 1: epilogue -> Q (x0.125)/K/V rounded fp16 [B,H,T,D]. MODE 0: fp32 out.
// ---------------------------------------------------------------------------
#define TSTRIDE 72
#define TILE_B  (128*TSTRIDE*2)          // 18432
#define STAGE_B (2*TILE_B)               // A + B = 36864
#define NSTAGE  3
#define GSMEM_TOTAL (NSTAGE*STAGE_B)     // 110592
#define NCHB    (KB_/64)                 // 16

template<int MODE>
__global__ __launch_bounds__(256)
void tgemm_kernel(const float* __restrict__ bias,
                  float* __restrict__ Cout,
                  int N)
{
    extern __shared__ char smc[];
    const uint32_t sb = smem_u32(smc);
    const int tid = threadIdx.x;
    const int wid = tid >> 5, lane = tid & 31;
    const int bx = blockIdx.x, by = blockIdx.y;
    const int wm = wid & 3;
    const int wn = wid >> 2;

    const __half* Abf = g_A + (size_t)(by * 128) * KB_;
    const __half* Bbf = (MODE ? g_Bqkv : g_Bout) + (size_t)(bx * 128) * KB_;

    const int lrow = tid >> 3;
    const int lch  = tid & 7;
    const uint32_t sOff = (uint32_t)(lrow * TSTRIDE * 2 + lch * 16);

    float acc[2][8][4];
#pragma unroll
    for (int i = 0; i < 2; i++)
#pragma unroll
        for (int j = 0; j < 8; j++)
#pragma unroll
            for (int v = 0; v < 4; v++) acc[i][j][v] = 0.f;

    const int a_row = (lane & 7) + ((lane >> 3) & 1) * 8;
    const int a_col = (lane >> 4) * 8;
    const int b_row = (lane & 7) + (lane >> 4) * 8;
    const int b_col = ((lane >> 3) & 1) * 8;
    const uint32_t aBaseRow = (uint32_t)(wm * 32 + a_row);
    const uint32_t bBaseRow = (uint32_t)(wn * 64 + b_row);

    auto load_stage = [&](int st, int ch) {
        const uint32_t sA = sb + st * STAGE_B + sOff;
        const uint32_t sB = sA + TILE_B;
        const __half* Ag = Abf + (size_t)lrow * KB_ + ch * 64 + lch * 8;
        const __half* Bg = Bbf + (size_t)lrow * KB_ + ch * 64 + lch * 8;
#pragma unroll
        for (int i = 0; i < 4; i++) {
            cp_async16(sA + i * 32 * TSTRIDE * 2, Ag + (size_t)(i * 32) * KB_);
            cp_async16(sB + i * 32 * TSTRIDE * 2, Bg + (size_t)(i * 32) * KB_);
        }
    };

#pragma unroll
    for (int s = 0; s < NSTAGE - 1; ++s) {
        load_stage(s, s);
        CP_COMMIT();
    }

    for (int ch = 0; ch < NCHB; ++ch) {
        CP_WAIT(NSTAGE - 2);
        __syncthreads();

        const int lc = ch + NSTAGE - 1;
        if (lc < NCHB) load_stage(lc % NSTAGE, lc);
        CP_COMMIT();

        const uint32_t sAp = sb + (ch % NSTAGE) * STAGE_B;
        const uint32_t sBp = sAp + TILE_B;
#pragma unroll
        for (int kk = 0; kk < 4; ++kk) {
            const int kc = kk * 16;
            uint32_t b[8][2];
#pragma unroll
            for (int np = 0; np < 4; ++np) {
                uint32_t addr = sBp + ((bBaseRow + np * 16) * TSTRIDE + kc + b_col) * 2;
                uint32_t r0, r1, r2, r3;
                ldsm_x4(r0, r1, r2, r3, addr);
                b[np*2][0] = r0; b[np*2][1] = r1;
                b[np*2+1][0] = r2; b[np*2+1][1] = r3;
            }
            uint32_t a[2][4];
#pragma unroll
            for (int mt = 0; mt < 2; ++mt) {
                uint32_t addr = sAp + ((aBaseRow + mt * 16) * TSTRIDE + kc + a_col) * 2;
                ldsm_x4(a[mt][0], a[mt][1], a[mt][2], a[mt][3], addr);
            }
#pragma unroll
            for (int mt = 0; mt < 2; ++mt)
#pragma unroll
                for (int nt = 0; nt < 8; ++nt)
                    mma_f16(acc[mt][nt], a[mt][0], a[mt][1], a[mt][2], a[mt][3],
                            b[nt][0], b[nt][1]);
        }
    }

    // -------- epilogue --------
    const int tr = lane >> 2;
    const int tc = (lane & 3) * 2;
#pragma unroll
    for (int mt = 0; mt < 2; ++mt) {
#pragma unroll
        for (int nt = 0; nt < 8; ++nt) {
            const int col = bx * 128 + wn * 64 + nt * 8 + tc;
            const float b0 = __ldg(bias + col);
            const float b1 = __ldg(bias + col + 1);
#pragma unroll
            for (int h2 = 0; h2 < 2; ++h2) {
                const int m = by * 128 + wm * 32 + mt * 16 + h2 * 8 + tr;
                float ox = acc[mt][nt][h2*2+0] + b0;
                float oy = acc[mt][nt][h2*2+1] + b1;
                if (MODE == 0) {
                    *(float2*)(Cout + (size_t)m * N + col) = make_float2(ox, oy);
                } else {
                    const int seg = col >> 10;
                    const int c = col & 1023;
                    const int h = c >> 6;
                    const int d = c & 63;
                    const int bb = m >> 10, t = m & 1023;
                    size_t idx = (((size_t)(bb * H_ + h)) * T_ + t) * D_ + d;
                    if (seg == 0) { ox *= 0.125f; oy *= 0.125f; }  // fold 1/sqrt(D)
                    uint32_t rw = pack_h2(__float2half(ox), __float2half(oy));
                    __half* dst = (seg == 0) ? g_Qf : (seg == 1) ? g_Kf : g_Vf;
                    *(uint32_t*)(dst + idx) = rw;
                }
            }
        }
    }
}

// ---------------------------------------------------------------------------
// fp16 HMMA flash attention, single-pass S and PV. CTA = 128 q-rows x (b,h).
// 8 warps, 16 rows each. K/V double-buffered cp.async. Heavy tiles first.
// Epilogue: O rounded fp16 -> g_A (head-interleaved [B*T, C]).
// ---------------------------------------------------------------------------
#define AST 72
#define QH_OFF 0
#define STG0   (128*AST*2)
#define KTILE_B (64*AST*2)
#define STG_B  (2*KTILE_B)
#define ASMEM_TOTAL (STG0 + 2*STG_B)   // 55296

__global__ __launch_bounds__(256)
void attn_kernel()
{
    extern __shared__ char smc[];
    const uint32_t sb = smem_u32(smc);
    const int tid = threadIdx.x, wid = tid >> 5, lane = tid & 31;
    const int qt = gridDim.x - 1 - blockIdx.x;   // heavy tiles first
    const int bh = blockIdx.y;
    const int q0 = qt * 128;
    const size_t base = (size_t)bh * T_ * D_;

    {
        const __half* Qf = g_Qf + base + (size_t)q0 * D_;
#pragma unroll
        for (int i = 0; i < 4; i++) {
            int idx = tid + i * 256;
            int r = idx >> 3, c = idx & 7;
            cp_async16(sb + QH_OFF + (uint32_t)(r * AST + c * 8) * 2, Qf + (size_t)r * 64 + c * 8);
        }
        CP_COMMIT();
    }

    const int KT = 2 * qt + 2;

    auto load_stage = [&](int st, int kt) {
        const uint32_t s0 = sb + STG0 + st * STG_B;
        const __half* srcs[2] = {
            g_Kf + base + (size_t)kt * 64 * D_,
            g_Vf + base + (size_t)kt * 64 * D_ };
#pragma unroll
        for (int tg = 0; tg < 2; tg++) {
#pragma unroll
            for (int it = 0; it < 2; it++) {
                int r = (tid >> 3) + it * 32, c = tid & 7;
                cp_async16(s0 + tg * KTILE_B + (uint32_t)(r * AST + c * 8) * 2,
                           srcs[tg] + (size_t)r * 64 + c * 8);
            }
        }
    };

    load_stage(0, 0); CP_COMMIT();

    const int a_row = (lane & 7) + ((lane >> 3) & 1) * 8;
    const int a_col = (lane >> 4) * 8;
    const int b_row = (lane & 7) + (lane >> 4) * 8;
    const int b_col = ((lane >> 3) & 1) * 8;
    const int v_row = lane & 15;
    const int v_col = (lane >> 4) * 8;
    const int wm = wid;

    uint32_t qh[4][4];
    float m_[2] = {-1e30f, -1e30f}, l_[2] = {0.f, 0.f};
    float oacc[8][4];
#pragma unroll
    for (int i = 0; i < 8; i++)
#pragma unroll
        for (int v = 0; v < 4; v++) oacc[i][v] = 0.f;

    const int rbase = q0 + wm * 16;

    for (int kt = 0; kt < KT; ++kt) {
        if (kt + 1 < KT) { load_stage((kt + 1) & 1, kt + 1); CP_COMMIT(); CP_WAIT(1); }
        else             { CP_WAIT(0); }
        __syncthreads();

        if (kt == 0) {
#pragma unroll
            for (int ks = 0; ks < 4; ks++) {
                uint32_t aq = sb + QH_OFF + (uint32_t)((wm * 16 + a_row) * AST + ks * 16 + a_col) * 2;
                ldsm_x4(qh[ks][0], qh[ks][1], qh[ks][2], qh[ks][3], aq);
            }
        }

        const bool active = (kt * 64) <= (rbase + 15);
        if (active) {
            const uint32_t sKf = sb + STG0 + (kt & 1) * STG_B;
            const uint32_t sVf = sKf + KTILE_B;

            // ---- S = Q*K (single pass) ----
            float sacc[8][4];
#pragma unroll
            for (int i = 0; i < 8; i++)
#pragma unroll
                for (int v = 0; v < 4; v++) sacc[i][v] = 0.f;

#pragma unroll
            for (int ks = 0; ks < 4; ks++) {
                uint32_t kf[4][4];
#pragma unroll
                for (int np = 0; np < 4; np++) {
                    uint32_t addr = sKf + (uint32_t)((np * 16 + b_row) * AST + ks * 16 + b_col) * 2;
                    ldsm_x4(kf[np][0], kf[np][1], kf[np][2], kf[np][3], addr);
                }
#pragma unroll
                for (int np = 0; np < 4; np++) {
                    mma_f16(sacc[2*np],   qh[ks][0], qh[ks][1], qh[ks][2], qh[ks][3], kf[np][0], kf[np][1]);
                    mma_f16(sacc[2*np+1], qh[ks][0], qh[ks][1], qh[ks][2], qh[ks][3], kf[np][2], kf[np][3]);
                }
            }

            if (kt * 64 + 63 > rbase) {
                const int r0r = rbase + (lane >> 2);
#pragma unroll
                for (int nt = 0; nt < 8; nt++) {
#pragma unroll
                    for (int v = 0; v < 4; v++) {
                        int col = kt * 64 + nt * 8 + 2 * (lane & 3) + (v & 1);
                        int row = r0r + (v >> 1) * 8;
                        if (col > row) sacc[nt][v] = -1e30f;
                    }
                }
            }

            float alpha[2];
#pragma unroll
            for (int h2 = 0; h2 < 2; h2++) {
                float mx = -1e30f;
#pragma unroll
                for (int nt = 0; nt < 8; nt++)
                    mx = fmaxf(mx, fmaxf(sacc[nt][2*h2], sacc[nt][2*h2+1]));
                mx = fmaxf(mx, __shfl_xor_sync(0xffffffffu, mx, 1));
                mx = fmaxf(mx, __shfl_xor_sync(0xffffffffu, mx, 2));
                float mnew = fmaxf(m_[h2], mx);
                alpha[h2] = __expf(m_[h2] - mnew);
                float rs = 0.f;
#pragma unroll
                for (int nt = 0; nt < 8; nt++) {
                    sacc[nt][2*h2]   = __expf(sacc[nt][2*h2]   - mnew);
                    sacc[nt][2*h2+1] = __expf(sacc[nt][2*h2+1] - mnew);
                    rs += sacc[nt][2*h2] + sacc[nt][2*h2+1];
                }
                rs += __shfl_xor_sync(0xffffffffu, rs, 1);
                rs += __shfl_xor_sync(0xffffffffu, rs, 2);
                l_[h2] = l_[h2] * alpha[h2] + rs;
                m_[h2] = mnew;
            }
#pragma unroll
            for (int dt = 0; dt < 8; dt++) {
                oacc[dt][0] *= alpha[0]; oacc[dt][1] *= alpha[0];
                oacc[dt][2] *= alpha[1]; oacc[dt][3] *= alpha[1];
            }

            // ---- O += P*V (single pass; P rounded fp16) ----
#pragma unroll
            for (int ks = 0; ks < 4; ks++) {
                uint32_t ph[4];
                ph[0] = pack_h2(__float2half(sacc[2*ks][0]),   __float2half(sacc[2*ks][1]));
                ph[1] = pack_h2(__float2half(sacc[2*ks][2]),   __float2half(sacc[2*ks][3]));
                ph[2] = pack_h2(__float2half(sacc[2*ks+1][0]), __float2half(sacc[2*ks+1][1]));
                ph[3] = pack_h2(__float2half(sacc[2*ks+1][2]), __float2half(sacc[2*ks+1][3]));

                uint32_t vf[4][4];
#pragma unroll
                for (int nt2 = 0; nt2 < 4; nt2++) {
                    uint32_t addr = sVf + (uint32_t)((ks * 16 + v_row) * AST + nt2 * 16 + v_col) * 2;
                    ldsm_x4_t(vf[nt2][0], vf[nt2][1], vf[nt2][2], vf[nt2][3], addr);
                }
#pragma unroll
                for (int nt2 = 0; nt2 < 4; nt2++) {
                    mma_f16(oacc[2*nt2],   ph[0], ph[1], ph[2], ph[3], vf[nt2][0], vf[nt2][1]);
                    mma_f16(oacc[2*nt2+1], ph[0], ph[1], ph[2], ph[3], vf[nt2][2], vf[nt2][3]);
                }
            }
        }
        __syncthreads();
    }

    // ---- epilogue: O/l rounded fp16 -> g_A ----
    const int bb = bh >> 4, hh = bh & 15;
    const float inv0 = 1.f / l_[0], inv1 = 1.f / l_[1];
#pragma unroll
    for (int dt = 0; dt < 8; dt++) {
#pragma unroll
        for (int h2 = 0; h2 < 2; h2++) {
            const int rloc = wm * 16 + (lane >> 2) + h2 * 8;
            const int d = dt * 8 + 2 * (lane & 3);
            const float inv = h2 ? inv1 : inv0;
            float ox = oacc[dt][2*h2]   * inv;
            float oy = oacc[dt][2*h2+1] * inv;
            uint32_t rw = pack_h2(__float2half(ox), __float2half(oy));
            const size_t mrow = (size_t)(bb * T_ + q0 + rloc);
            *(uint32_t*)(g_A + mrow * Cc_ + hh * 64 + d) = rw;
        }
    }
}

// ---------------------------------------------------------------------------
extern "C" void kernel_launch(void* const* d_in, const int* in_sizes, int n_in,
                              void* d_out, int out_size)
{
    const float* x    = (const float*)d_in[0];
    const float* Wqkv = (const float*)d_in[1];
    const float* bqkv = (const float*)d_in[2];
    const float* Wout = (const float*)d_in[3];
    const float* bout = (const float*)d_in[4];
    float* out = (float*)d_out;

    cudaFuncSetAttribute(tgemm_kernel<1>,
                         cudaFuncAttributeMaxDynamicSharedMemorySize, GSMEM_TOTAL);
    cudaFuncSetAttribute(tgemm_kernel<0>,
                         cudaFuncAttributeMaxDynamicSharedMemorySize, GSMEM_TOTAL);
    cudaFuncSetAttribute(attn_kernel,
                         cudaFuncAttributeMaxDynamicSharedMemorySize, ASMEM_TOTAL);

    // 0) conversions (round everything to fp16)
    conv_w<1><<<dim3(Cc_/32, N3_/32), 256>>>(Wqkv, N3_);
    conv_w<0><<<dim3(Cc_/32, Cc_/32), 256>>>(Wout, Cc_);
    conv_act<<<M_*Cc_/4/256, 256>>>(x);

    // 1) QKV projection (single-pass fp16) -> Q(x0.125)/K/V fp16 [B,H,T,D]
    tgemm_kernel<1><<<dim3(N3_/128, M_/128), 256, GSMEM_TOTAL>>>(bqkv, nullptr, N3_);

    // 2) fp16 HMMA causal flash attention -> g_A (fp16, [B*T, C])
    attn_kernel<<<dim3(T_/128, BH_), 256, ASMEM_TOTAL>>>();

    // 3) output projection (single-pass fp16) -> d_out
    tgemm_kernel<0><<<dim3(Cc_/128, M_/128), 256, GSMEM_TOTAL>>>(bout, out, Cc_);
}

// round 11
// speedup vs baseline: 2.9707x; 1.0020x over previous
#include <cuda_runtime.h>
#include <cuda_fp16.h>
#include <cstdint>

// Problem constants
#define B_   8
#define T_   1024
#define Cc_  1024
#define H_   16
#define D_   64
#define BH_  (B_*H_)     // 128
#define M_   (B_*T_)     // 8192
#define N3_  3072
#define KB_  Cc_         // 1024

// Scratch (static device globals: allocation-free)
__device__ __half g_Qf[(size_t)BH_*T_*D_];
__device__ __half g_Kf[(size_t)BH_*T_*D_];
__device__ __half g_Vf[(size_t)BH_*T_*D_];
__device__ __half g_A[(size_t)M_*Cc_];       // acts fp16: x for QKV, then O for proj
__device__ __half g_Bqkv[(size_t)N3_*KB_];
__device__ __half g_Bout[(size_t)Cc_*KB_];

// ---------------------------------------------------------------------------
__device__ __forceinline__ uint32_t smem_u32(const void* p) {
    uint32_t a;
    asm("{ .reg .u64 t; cvta.to.shared.u64 t, %1; cvt.u32.u64 %0, t; }"
        : "=r"(a) : "l"(p));
    return a;
}
__device__ __forceinline__ void ldsm_x4(uint32_t& r0, uint32_t& r1,
                                        uint32_t& r2, uint32_t& r3, uint32_t addr) {
    asm volatile("ldmatrix.sync.aligned.m8n8.x4.shared.b16 {%0,%1,%2,%3}, [%4];"
                 : "=r"(r0), "=r"(r1), "=r"(r2), "=r"(r3) : "r"(addr));
}
__device__ __forceinline__ void ldsm_x4_t(uint32_t& r0, uint32_t& r1,
                                          uint32_t& r2, uint32_t& r3, uint32_t addr) {
    asm volatile("ldmatrix.sync.aligned.m8n8.x4.trans.shared.b16 {%0,%1,%2,%3}, [%4];"
                 : "=r"(r0), "=r"(r1), "=r"(r2), "=r"(r3) : "r"(addr));
}
__device__ __forceinline__ void mma_f16(float* d, uint32_t a0, uint32_t a1,
                                        uint32_t a2, uint32_t a3,
                                        uint32_t b0, uint32_t b1) {
    asm volatile(
        "mma.sync.aligned.m16n8k16.row.col.f32.f16.f16.f32 "
        "{%0,%1,%2,%3}, {%4,%5,%6,%7}, {%8,%9}, {%0,%1,%2,%3};"
        : "+f"(d[0]), "+f"(d[1]), "+f"(d[2]), "+f"(d[3])
        : "r"(a0), "r"(a1), "r"(a2), "r"(a3), "r"(b0), "r"(b1));
}
__device__ __forceinline__ void cp_async16(uint32_t saddr, const void* gaddr) {
    asm volatile("cp.async.cg.shared.global [%0], [%1], 16;"
                 :: "r"(saddr), "l"(gaddr));
}
#define CP_COMMIT() asm volatile("cp.async.commit_group;" ::: "memory")
#define CP_WAIT(n)  asm volatile("cp.async.wait_group %0;" :: "n"(n) : "memory")

__device__ __forceinline__ uint32_t pack_h2(__half a, __half b) {
    return (uint32_t)__half_as_ushort(a) | ((uint32_t)__half_as_ushort(b) << 16);
}

// ---------------------------------------------------------------------------
// Conversion kernels (round to fp16)
// ---------------------------------------------------------------------------
__global__ __launch_bounds__(256)
void conv_act(const float* __restrict__ src)
{
    int idx = blockIdx.x * 256 + threadIdx.x;
    int m  = idx >> 8;
    int k4 = (idx & 255) << 2;
    float4 v = *(const float4*)(src + (size_t)m * Cc_ + k4);
    uint2 w = make_uint2(pack_h2(__float2half(v.x), __float2half(v.y)),
                         pack_h2(__float2half(v.z), __float2half(v.w)));
    *(uint2*)(g_A + (size_t)m * Cc_ + k4) = w;
}

template<int WSEL>
__global__ __launch_bounds__(256)
void conv_w(const float* __restrict__ W, int N)
{
    __shared__ float tile[32][33];
    __half* Bt = WSEL ? g_Bqkv : g_Bout;
    const int k0 = blockIdx.x * 32, n0 = blockIdx.y * 32;
    const int t = threadIdx.x;
#pragma unroll
    for (int i = 0; i < 4; i++) {
        int r = (t >> 5) + i * 8;
        int c = t & 31;
        tile[r][c] = W[(size_t)(k0 + r) * N + n0 + c];
    }
    __syncthreads();
#pragma unroll
    for (int i = 0; i < 4; i++) {
        int nr = (t >> 5) + i * 8;
        int kc = t & 31;
        Bt[(size_t)(n0 + nr) * KB_ + k0 + kc] = __float2half(tile[kc][nr]);
    }
}

// ---------------------------------------------------------------------------
// fp16 HMMA GEMM: 64x128 CTA tile, BK=64, 8 warps (2M x 4N, warp 32x32),
// 2-stage cp.async, one barrier per chunk, 3 CTAs/SM. K=1024 (16 chunks).
// MODE 1: epilogue -> Q(x0.125)/K/V rounded fp16 [B,H,T,D]. MODE 0: fp32 out.
// ---------------------------------------------------------------------------
#define TSTRIDE 72
#define ATILE_B (64*TSTRIDE*2)           // 9216
#define BTILE_B (128*TSTRIDE*2)          // 18432
#define STAGE_B (ATILE_B + BTILE_B)      // 27648
#define NSTAGE  2
#define GSMEM_TOTAL (NSTAGE*STAGE_B)     // 55296
#define NCHB    (KB_/64)                 // 16

template<int MODE>
__global__ __launch_bounds__(256, 3)
void tgemm_kernel(const float* __restrict__ bias,
                  float* __restrict__ Cout,
                  int N)
{
    extern __shared__ char smc[];
    const uint32_t sb = smem_u32(smc);
    const int tid = threadIdx.x;
    const int wid = tid >> 5, lane = tid & 31;
    const int bx = blockIdx.x, by = blockIdx.y;
    const int wm = wid & 1;          // 2 warp rows (32 m each)
    const int wn = wid >> 1;         // 4 warp cols (32 n each)

    const __half* Abf = g_A + (size_t)(by * 64) * KB_;
    const __half* Bbf = (MODE ? g_Bqkv : g_Bout) + (size_t)(bx * 128) * KB_;

    const int lrow = tid >> 3;          // 0..31
    const int lch  = tid & 7;           // 0..7
    const uint32_t sOff = (uint32_t)(lrow * TSTRIDE * 2 + lch * 16);

    float acc[2][4][4];
#pragma unroll
    for (int i = 0; i < 2; i++)
#pragma unroll
        for (int j = 0; j < 4; j++)
#pragma unroll
            for (int v = 0; v < 4; v++) acc[i][j][v] = 0.f;

    const int a_row = (lane & 7) + ((lane >> 3) & 1) * 8;
    const int a_col = (lane >> 4) * 8;
    const int b_row = (lane & 7) + (lane >> 4) * 8;
    const int b_col = ((lane >> 3) & 1) * 8;
    const uint32_t aBaseRow = (uint32_t)(wm * 32 + a_row);
    const uint32_t bBaseRow = (uint32_t)(wn * 32 + b_row);

    auto load_stage = [&](int st, int ch) {
        const uint32_t sA = sb + st * STAGE_B + sOff;
        const uint32_t sB = sb + st * STAGE_B + ATILE_B + sOff;
        const __half* Ag = Abf + (size_t)lrow * KB_ + ch * 64 + lch * 8;
        const __half* Bg = Bbf + (size_t)lrow * KB_ + ch * 64 + lch * 8;
#pragma unroll
        for (int i = 0; i < 2; i++)
            cp_async16(sA + i * 32 * TSTRIDE * 2, Ag + (size_t)(i * 32) * KB_);
#pragma unroll
        for (int i = 0; i < 4; i++)
            cp_async16(sB + i * 32 * TSTRIDE * 2, Bg + (size_t)(i * 32) * KB_);
    };

    load_stage(0, 0);
    CP_COMMIT();

    for (int ch = 0; ch < NCHB; ++ch) {
        CP_WAIT(0);               // stage ch resident
        __syncthreads();          // + all warps done reading stage ch-1

        if (ch + 1 < NCHB) { load_stage((ch + 1) & 1, ch + 1); CP_COMMIT(); }

        const uint32_t sAp = sb + (ch & 1) * STAGE_B;
        const uint32_t sBp = sAp + ATILE_B;
#pragma unroll
        for (int kk = 0; kk < 4; ++kk) {
            const int kc = kk * 16;
            uint32_t b[4][2];
#pragma unroll
            for (int np = 0; np < 2; ++np) {
                uint32_t addr = sBp + ((bBaseRow + np * 16) * TSTRIDE + kc + b_col) * 2;
                uint32_t r0, r1, r2, r3;
                ldsm_x4(r0, r1, r2, r3, addr);
                b[np*2][0] = r0; b[np*2][1] = r1;
                b[np*2+1][0] = r2; b[np*2+1][1] = r3;
            }
            uint32_t a[2][4];
#pragma unroll
            for (int mt = 0; mt < 2; ++mt) {
                uint32_t addr = sAp + ((aBaseRow + mt * 16) * TSTRIDE + kc + a_col) * 2;
                ldsm_x4(a[mt][0], a[mt][1], a[mt][2], a[mt][3], addr);
            }
#pragma unroll
            for (int mt = 0; mt < 2; ++mt)
#pragma unroll
                for (int nt = 0; nt < 4; ++nt)
                    mma_f16(acc[mt][nt], a[mt][0], a[mt][1], a[mt][2], a[mt][3],
                            b[nt][0], b[nt][1]);
        }
    }

    // -------- epilogue --------
    const int tr = lane >> 2;
    const int tc = (lane & 3) * 2;
#pragma unroll
    for (int mt = 0; mt < 2; ++mt) {
#pragma unroll
        for (int nt = 0; nt < 4; ++nt) {
            const int col = bx * 128 + wn * 32 + nt * 8 + tc;
            const float b0 = __ldg(bias + col);
            const float b1 = __ldg(bias + col + 1);
#pragma unroll
            for (int h2 = 0; h2 < 2; ++h2) {
                const int m = by * 64 + wm * 32 + mt * 16 + h2 * 8 + tr;
                float ox = acc[mt][nt][h2*2+0] + b0;
                float oy = acc[mt][nt][h2*2+1] + b1;
                if (MODE == 0) {
                    *(float2*)(Cout + (size_t)m * N + col) = make_float2(ox, oy);
                } else {
                    const int seg = col >> 10;
                    const int c = col & 1023;
                    const int h = c >> 6;
                    const int d = c & 63;
                    const int bb = m >> 10, t = m & 1023;
                    size_t idx = (((size_t)(bb * H_ + h)) * T_ + t) * D_ + d;
                    if (seg == 0) { ox *= 0.125f; oy *= 0.125f; }  // fold 1/sqrt(D)
                    uint32_t rw = pack_h2(__float2half(ox), __float2half(oy));
                    __half* dst = (seg == 0) ? g_Qf : (seg == 1) ? g_Kf : g_Vf;
                    *(uint32_t*)(dst + idx) = rw;
                }
            }
        }
    }
}

// ---------------------------------------------------------------------------
// fp16 HMMA flash attention (unchanged from R10)
// ---------------------------------------------------------------------------
#define AST 72
#define QH_OFF 0
#define STG0   (128*AST*2)
#define KTILE_B (64*AST*2)
#define STG_B  (2*KTILE_B)
#define ASMEM_TOTAL (STG0 + 2*STG_B)   // 55296

__global__ __launch_bounds__(256)
void attn_kernel()
{
    extern __shared__ char smc[];
    const uint32_t sb = smem_u32(smc);
    const int tid = threadIdx.x, wid = tid >> 5, lane = tid & 31;
    const int qt = gridDim.x - 1 - blockIdx.x;   // heavy tiles first
    const int bh = blockIdx.y;
    const int q0 = qt * 128;
    const size_t base = (size_t)bh * T_ * D_;

    {
        const __half* Qf = g_Qf + base + (size_t)q0 * D_;
#pragma unroll
        for (int i = 0; i < 4; i++) {
            int idx = tid + i * 256;
            int r = idx >> 3, c = idx & 7;
            cp_async16(sb + QH_OFF + (uint32_t)(r * AST + c * 8) * 2, Qf + (size_t)r * 64 + c * 8);
        }
        CP_COMMIT();
    }

    const int KT = 2 * qt + 2;

    auto load_stage = [&](int st, int kt) {
        const uint32_t s0 = sb + STG0 + st * STG_B;
        const __half* srcs[2] = {
            g_Kf + base + (size_t)kt * 64 * D_,
            g_Vf + base + (size_t)kt * 64 * D_ };
#pragma unroll
        for (int tg = 0; tg < 2; tg++) {
#pragma unroll
            for (int it = 0; it < 2; it++) {
                int r = (tid >> 3) + it * 32, c = tid & 7;
                cp_async16(s0 + tg * KTILE_B + (uint32_t)(r * AST + c * 8) * 2,
                           srcs[tg] + (size_t)r * 64 + c * 8);
            }
        }
    };

    load_stage(0, 0); CP_COMMIT();

    const int a_row = (lane & 7) + ((lane >> 3) & 1) * 8;
    const int a_col = (lane >> 4) * 8;
    const int b_row = (lane & 7) + (lane >> 4) * 8;
    const int b_col = ((lane >> 3) & 1) * 8;
    const int v_row = lane & 15;
    const int v_col = (lane >> 4) * 8;
    const int wm = wid;

    uint32_t qh[4][4];
    float m_[2] = {-1e30f, -1e30f}, l_[2] = {0.f, 0.f};
    float oacc[8][4];
#pragma unroll
    for (int i = 0; i < 8; i++)
#pragma unroll
        for (int v = 0; v < 4; v++) oacc[i][v] = 0.f;

    const int rbase = q0 + wm * 16;

    for (int kt = 0; kt < KT; ++kt) {
        if (kt + 1 < KT) { load_stage((kt + 1) & 1, kt + 1); CP_COMMIT(); CP_WAIT(1); }
        else             { CP_WAIT(0); }
        __syncthreads();

        if (kt == 0) {
#pragma unroll
            for (int ks = 0; ks < 4; ks++) {
                uint32_t aq = sb + QH_OFF + (uint32_t)((wm * 16 + a_row) * AST + ks * 16 + a_col) * 2;
                ldsm_x4(qh[ks][0], qh[ks][1], qh[ks][2], qh[ks][3], aq);
            }
        }

        const bool active = (kt * 64) <= (rbase + 15);
        if (active) {
            const uint32_t sKf = sb + STG0 + (kt & 1) * STG_B;
            const uint32_t sVf = sKf + KTILE_B;

            float sacc[8][4];
#pragma unroll
            for (int i = 0; i < 8; i++)
#pragma unroll
                for (int v = 0; v < 4; v++) sacc[i][v] = 0.f;

#pragma unroll
            for (int ks = 0; ks < 4; ks++) {
                uint32_t kf[4][4];
#pragma unroll
                for (int np = 0; np < 4; np++) {
                    uint32_t addr = sKf + (uint32_t)((np * 16 + b_row) * AST + ks * 16 + b_col) * 2;
                    ldsm_x4(kf[np][0], kf[np][1], kf[np][2], kf[np][3], addr);
                }
#pragma unroll
                for (int np = 0; np < 4; np++) {
                    mma_f16(sacc[2*np],   qh[ks][0], qh[ks][1], qh[ks][2], qh[ks][3], kf[np][0], kf[np][1]);
                    mma_f16(sacc[2*np+1], qh[ks][0], qh[ks][1], qh[ks][2], qh[ks][3], kf[np][2], kf[np][3]);
                }
            }

            if (kt * 64 + 63 > rbase) {
                const int r0r = rbase + (lane >> 2);
#pragma unroll
                for (int nt = 0; nt < 8; nt++) {
#pragma unroll
                    for (int v = 0; v < 4; v++) {
                        int col = kt * 64 + nt * 8 + 2 * (lane & 3) + (v & 1);
                        int row = r0r + (v >> 1) * 8;
                        if (col > row) sacc[nt][v] = -1e30f;
                    }
                }
            }

            float alpha[2];
#pragma unroll
            for (int h2 = 0; h2 < 2; h2++) {
                float mx = -1e30f;
#pragma unroll
                for (int nt = 0; nt < 8; nt++)
                    mx = fmaxf(mx, fmaxf(sacc[nt][2*h2], sacc[nt][2*h2+1]));
                mx = fmaxf(mx, __shfl_xor_sync(0xffffffffu, mx, 1));
                mx = fmaxf(mx, __shfl_xor_sync(0xffffffffu, mx, 2));
                float mnew = fmaxf(m_[h2], mx);
                alpha[h2] = __expf(m_[h2] - mnew);
                float rs = 0.f;
#pragma unroll
                for (int nt = 0; nt < 8; nt++) {
                    sacc[nt][2*h2]   = __expf(sacc[nt][2*h2]   - mnew);
                    sacc[nt][2*h2+1] = __expf(sacc[nt][2*h2+1] - mnew);
                    rs += sacc[nt][2*h2] + sacc[nt][2*h2+1];
                }
                rs += __shfl_xor_sync(0xffffffffu, rs, 1);
                rs += __shfl_xor_sync(0xffffffffu, rs, 2);
                l_[h2] = l_[h2] * alpha[h2] + rs;
                m_[h2] = mnew;
            }
#pragma unroll
            for (int dt = 0; dt < 8; dt++) {
                oacc[dt][0] *= alpha[0]; oacc[dt][1] *= alpha[0];
                oacc[dt][2] *= alpha[1]; oacc[dt][3] *= alpha[1];
            }

#pragma unroll
            for (int ks = 0; ks < 4; ks++) {
                uint32_t ph[4];
                ph[0] = pack_h2(__float2half(sacc[2*ks][0]),   __float2half(sacc[2*ks][1]));
                ph[1] = pack_h2(__float2half(sacc[2*ks][2]),   __float2half(sacc[2*ks][3]));
                ph[2] = pack_h2(__float2half(sacc[2*ks+1][0]), __float2half(sacc[2*ks+1][1]));
                ph[3] = pack_h2(__float2half(sacc[2*ks+1][2]), __float2half(sacc[2*ks+1][3]));

                uint32_t vf[4][4];
#pragma unroll
                for (int nt2 = 0; nt2 < 4; nt2++) {
                    uint32_t addr = sVf + (uint32_t)((ks * 16 + v_row) * AST + nt2 * 16 + v_col) * 2;
                    ldsm_x4_t(vf[nt2][0], vf[nt2][1], vf[nt2][2], vf[nt2][3], addr);
                }
#pragma unroll
                for (int nt2 = 0; nt2 < 4; nt2++) {
                    mma_f16(oacc[2*nt2],   ph[0], ph[1], ph[2], ph[3], vf[nt2][0], vf[nt2][1]);
                    mma_f16(oacc[2*nt2+1], ph[0], ph[1], ph[2], ph[3], vf[nt2][2], vf[nt2][3]);
                }
            }
        }
        __syncthreads();
    }

    const int bb = bh >> 4, hh = bh & 15;
    const float inv0 = 1.f / l_[0], inv1 = 1.f / l_[1];
#pragma unroll
    for (int dt = 0; dt < 8; dt++) {
#pragma unroll
        for (int h2 = 0; h2 < 2; h2++) {
            const int rloc = wm * 16 + (lane >> 2) + h2 * 8;
            const int d = dt * 8 + 2 * (lane & 3);
            const float inv = h2 ? inv1 : inv0;
            float ox = oacc[dt][2*h2]   * inv;
            float oy = oacc[dt][2*h2+1] * inv;
            uint32_t rw = pack_h2(__float2half(ox), __float2half(oy));
            const size_t mrow = (size_t)(bb * T_ + q0 + rloc);
            *(uint32_t*)(g_A + mrow * Cc_ + hh * 64 + d) = rw;
        }
    }
}

// ---------------------------------------------------------------------------
extern "C" void kernel_launch(void* const* d_in, const int* in_sizes, int n_in,
                              void* d_out, int out_size)
{
    const float* x    = (const float*)d_in[0];
    const float* Wqkv = (const float*)d_in[1];
    const float* bqkv = (const float*)d_in[2];
    const float* Wout = (const float*)d_in[3];
    const float* bout = (const float*)d_in[4];
    float* out = (float*)d_out;

    cudaFuncSetAttribute(tgemm_kernel<1>,
                         cudaFuncAttributeMaxDynamicSharedMemorySize, GSMEM_TOTAL);
    cudaFuncSetAttribute(tgemm_kernel<0>,
                         cudaFuncAttributeMaxDynamicSharedMemorySize, GSMEM_TOTAL);
    cudaFuncSetAttribute(attn_kernel,
                         cudaFuncAttributeMaxDynamicSharedMemorySize, ASMEM_TOTAL);

    // 0) conversions (round everything to fp16)
    conv_w<1><<<dim3(Cc_/32, N3_/32), 256>>>(Wqkv, N3_);
    conv_w<0><<<dim3(Cc_/32, Cc_/32), 256>>>(Wout, Cc_);
    conv_act<<<M_*Cc_/4/256, 256>>>(x);

    // 1) QKV projection (64x128 tiles, 3 CTAs/SM) -> Q(x0.125)/K/V fp16
    tgemm_kernel<1><<<dim3(N3_/128, M_/64), 256, GSMEM_TOTAL>>>(bqkv, nullptr, N3_);

    // 2) fp16 HMMA causal flash attention -> g_A (fp16, [B*T, C])
    attn_kernel<<<dim3(T_/128, BH_), 256, ASMEM_TOTAL>>>();

    // 3) output projection (64x128 tiles) -> d_out
    tgemm_kernel<0><<<dim3(Cc_/128, M_/64), 256, GSMEM_TOTAL>>>(bout, out, Cc_);
}